// round 8
// baseline (speedup 1.0000x reference)
#include <cuda_runtime.h>
#include <cstddef>
#include <cstdint>
#include <math.h>

#define BATCH 128

typedef unsigned long long ull;

// ---------------------------------------------------------------------------
// f32x2 packed helpers (sm_103a): 2 fp32 ops per issue slot, exact fp32.
// ---------------------------------------------------------------------------
__device__ __forceinline__ ull pack2(float lo, float hi) {
    ull r;
    asm("mov.b64 %0, {%1, %2};" : "=l"(r) : "f"(lo), "f"(hi));
    return r;
}
__device__ __forceinline__ void unpack2(ull v, float& lo, float& hi) {
    asm("mov.b64 {%0, %1}, %2;" : "=f"(lo), "=f"(hi) : "l"(v));
}
__device__ __forceinline__ ull ffma2(ull a, ull b, ull c) {
    ull d;
    asm("fma.rn.f32x2 %0, %1, %2, %3;" : "=l"(d) : "l"(a), "l"(b), "l"(c));
    return d;
}
__device__ __forceinline__ ull add2(ull a, ull b) {
    ull d;
    asm("add.rn.f32x2 %0, %1, %2;" : "=l"(d) : "l"(a), "l"(b));
    return d;
}

// ---------------------------------------------------------------------------
// Scratch (no allocations allowed).
// ---------------------------------------------------------------------------
constexpr size_t N_BUF1 = (size_t)BATCH * 96 * 32 * 32;   // conv1 out
constexpr size_t N_BUF2 = (size_t)BATCH * 96 * 16 * 16;   // pool1
constexpr size_t N_BUF3 = (size_t)BATCH * 256 * 16 * 16;  // conv2 out
constexpr size_t N_BUF4 = (size_t)BATCH * 256 * 8 * 8;    // pool2
constexpr size_t N_BUF5 = (size_t)BATCH * 384 * 8 * 8;    // conv3 out
constexpr size_t N_BUF6 = (size_t)BATCH * 256 * 6 * 6;    // pcaps out
constexpr size_t N_U    = (size_t)BATCH * 1152 * 8;       // squashed caps
constexpr size_t N_BLOG = (size_t)BATCH * 100 * 1152;
constexpr size_t N_C    = (size_t)BATCH * 100 * 1152;
constexpr size_t N_V    = (size_t)BATCH * 100 * 16;
constexpr size_t N_F1   = (size_t)BATCH * 4096;
constexpr size_t N_F2   = (size_t)BATCH * 4096;

constexpr size_t O_BUF1 = 0;
constexpr size_t O_BUF2 = O_BUF1 + N_BUF1;
constexpr size_t O_BUF3 = O_BUF2 + N_BUF2;
constexpr size_t O_BUF4 = O_BUF3 + N_BUF3;
constexpr size_t O_BUF5 = O_BUF4 + N_BUF4;
constexpr size_t O_BUF6 = O_BUF5 + N_BUF5;
constexpr size_t O_U    = O_BUF6 + N_BUF6;
constexpr size_t O_BLOG = O_U + N_U;
constexpr size_t O_C    = O_BLOG + N_BLOG;
constexpr size_t O_V    = O_C + N_C;
constexpr size_t O_F1   = O_V + N_V;
constexpr size_t O_F2   = O_F1 + N_F1;
constexpr size_t N_TOTAL = O_F2 + N_F2;

__device__ __align__(16) float g_scratch[N_TOTAL];

// ---------------------------------------------------------------------------
// Direct 3x3 conv (stride 1), packed f32x2 FMAs (unchanged from passing R6).
// ---------------------------------------------------------------------------
template<int CIN, int HIN, int WIN, int COUT, int HOUT, int WOUT, int PAD,
         int ICC, int PPT, int NOCSUB, bool RELU>
__global__ void conv3x3_kernel(const float* __restrict__ in,
                               const float* __restrict__ wt,
                               const float* __restrict__ bias,
                               float* __restrict__ out)
{
    constexpr int NPG = (HOUT * WOUT) / PPT;
    constexpr int NT  = NPG * NOCSUB;
    constexpr int OCB = NOCSUB * 8;
    constexpr int HT  = HIN + 2 * PAD;
    constexpr int WT  = WIN + 2 * PAD;
    constexpr int WTP = WT + 1;

    __shared__ __align__(16) ull in_s2[ICC * HT * WTP];
    __shared__ __align__(16) float w_s[ICC * 9 * OCB];

    const int tid   = threadIdx.x;
    const int ocblk = blockIdx.x;
    const int b     = blockIdx.y;

    const int pg  = tid % NPG;
    const int ocs = tid / NPG;
    const int oc0 = ocblk * OCB + ocs * 8;

    int rows[PPT], cols[PPT];
    #pragma unroll
    for (int q = 0; q < PPT; q++) {
        int P = pg + q * NPG;
        rows[q] = P / WOUT;
        cols[q] = P % WOUT;
    }

    ull acc2[PPT][4];
    #pragma unroll
    for (int j4 = 0; j4 < 4; j4++) {
        ull bp = pack2(bias[oc0 + 2 * j4], bias[oc0 + 2 * j4 + 1]);
        #pragma unroll
        for (int p = 0; p < PPT; p++) acc2[p][j4] = bp;
    }

    for (int ic0 = 0; ic0 < CIN; ic0 += ICC) {
        __syncthreads();
        for (int idx = tid; idx < ICC * HT * WT; idx += NT) {
            int x  = idx % WT;
            int y  = (idx / WT) % HT;
            int ic = idx / (WT * HT);
            int gy = y - PAD, gx = x - PAD;
            float v = 0.f;
            if (gy >= 0 && gy < HIN && gx >= 0 && gx < WIN)
                v = in[((size_t)(b * CIN + ic0 + ic) * HIN + gy) * WIN + gx];
            in_s2[(ic * HT + y) * WTP + x] = pack2(v, v);
        }
        for (int idx = tid; idx < ICC * 9 * OCB; idx += NT) {
            int oc_l = idx % OCB;
            int tap  = (idx / OCB) % 9;
            int ic   = idx / (OCB * 9);
            w_s[(ic * 9 + tap) * OCB + oc_l] =
                wt[((size_t)(ocblk * OCB + oc_l) * CIN + ic0 + ic) * 9 + tap];
        }
        __syncthreads();

        #pragma unroll
        for (int ic = 0; ic < ICC; ic++) {
            #pragma unroll
            for (int ky = 0; ky < 3; ky++) {
                ull xv[PPT][3];
                #pragma unroll
                for (int q = 0; q < PPT; q++) {
                    int base = (ic * HT + rows[q] + ky) * WTP + cols[q];
                    xv[q][0] = in_s2[base + 0];
                    xv[q][1] = in_s2[base + 1];
                    xv[q][2] = in_s2[base + 2];
                }
                #pragma unroll
                for (int kx = 0; kx < 3; kx++) {
                    const ulonglong2* wp = reinterpret_cast<const ulonglong2*>(
                        &w_s[(ic * 9 + ky * 3 + kx) * OCB + ocs * 8]);
                    ulonglong2 wA = wp[0];
                    ulonglong2 wB = wp[1];
                    #pragma unroll
                    for (int q = 0; q < PPT; q++) {
                        ull xq = xv[q][kx];
                        acc2[q][0] = ffma2(xq, wA.x, acc2[q][0]);
                        acc2[q][1] = ffma2(xq, wA.y, acc2[q][1]);
                        acc2[q][2] = ffma2(xq, wB.x, acc2[q][2]);
                        acc2[q][3] = ffma2(xq, wB.y, acc2[q][3]);
                    }
                }
            }
        }
    }

    #pragma unroll
    for (int j4 = 0; j4 < 4; j4++) {
        #pragma unroll
        for (int q = 0; q < PPT; q++) {
            float lo, hi;
            unpack2(acc2[q][j4], lo, hi);
            if (RELU) { lo = fmaxf(lo, 0.f); hi = fmaxf(hi, 0.f); }
            size_t ob = ((size_t)(b * COUT + oc0 + 2 * j4) * HOUT + rows[q]) * WOUT + cols[q];
            out[ob] = lo;
            out[ob + (size_t)HOUT * WOUT] = hi;
        }
    }
}

// ---------------------------------------------------------------------------
// MaxPool 3x3 stride 2 pad 1
// ---------------------------------------------------------------------------
template<int C, int HIN>
__global__ void maxpool_kernel(const float* __restrict__ in, float* __restrict__ out)
{
    constexpr int HO = HIN / 2;
    int idx = blockIdx.x * blockDim.x + threadIdx.x;
    if (idx >= BATCH * C * HO * HO) return;
    int ox = idx % HO;
    int oy = (idx / HO) % HO;
    int c  = (idx / (HO * HO)) % C;
    int b  = idx / (HO * HO * C);
    const float* p = in + ((size_t)(b * C + c)) * HIN * HIN;
    float m = -1e30f;
    #pragma unroll
    for (int dy = 0; dy < 3; dy++) {
        int y = 2 * oy - 1 + dy;
        if (y < 0 || y >= HIN) continue;
        #pragma unroll
        for (int dx = 0; dx < 3; dx++) {
            int x = 2 * ox - 1 + dx;
            if (x < 0 || x >= HIN) continue;
            m = fmaxf(m, p[y * HIN + x]);
        }
    }
    out[idx] = m;
}

// ---------------------------------------------------------------------------
// Squash primarycaps: p flat [B,9216] -> u [B,1152,8]
// ---------------------------------------------------------------------------
__global__ void squash_u_kernel(const float* __restrict__ p, float* __restrict__ u)
{
    int cap = blockIdx.x * blockDim.x + threadIdx.x;
    if (cap >= BATCH * 1152) return;
    const float4* s = reinterpret_cast<const float4*>(p + (size_t)cap * 8);
    float4 a = s[0], b4 = s[1];
    float n2 = a.x * a.x + a.y * a.y + a.z * a.z + a.w * a.w +
               b4.x * b4.x + b4.y * b4.y + b4.z * b4.z + b4.w * b4.w;
    float sc = (n2 / (1.f + n2)) * rsqrtf(n2 + 1e-8f);
    float4* o = reinterpret_cast<float4*>(u + (size_t)cap * 8);
    o[0] = make_float4(a.x * sc, a.y * sc, a.z * sc, a.w * sc);
    o[1] = make_float4(b4.x * sc, b4.y * sc, b4.z * sc, b4.w * sc);
}

// ---------------------------------------------------------------------------
// route_s_gemm<MODE>: s[b,o,d] = sum_{i,e} W[o,i,d,e] * (c[b,o,i]*u[b,i,e]),
// then v[b,o,:] = squash(s). MODE 0: c = 0.01 uniform; else read c.
// Grid (100 o, 8 bg). Block 128 = 16 b x 8 d-pairs. W chunk transposed in
// smem to [il][ep][d] (u64 e-pairs) -> LDS.128 over consecutive d, conflict-
// free; cu (= c*u) packed e-pairs, broadcast per-b.
// ---------------------------------------------------------------------------
template<int MODE>
__global__ void route_s_gemm(const float* __restrict__ Wc,
                             const float* __restrict__ u,
                             const float* __restrict__ c,
                             float* __restrict__ v)
{
    __shared__ __align__(16) ull W2_s[32 * 4 * 16];   // [(il*4+ep)*16 + d]  16KB
    __shared__ __align__(16) ull cu2_s[16 * 32 * 4];  // [(b*32+il)*4 + ep]  16KB
    __shared__ float ss[16][17];

    const int o   = blockIdx.x;
    const int bg  = blockIdx.y;
    const int tid = threadIdx.x;
    const int dp  = tid & 7;      // d-pair: d0 = 2dp, d1 = 2dp+1
    const int bl  = tid >> 3;     // local batch 0..15
    const int b   = bg * 16 + bl;

    ull accA0 = 0ull, accA1 = 0ull;  // d0: even/odd ep
    ull accB0 = 0ull, accB1 = 0ull;  // d1

    for (int i0 = 0; i0 < 1152; i0 += 32) {
        __syncthreads();
        // build cu2_s: 2048 u64; idx = (bb*32+il)*4+ep
        #pragma unroll
        for (int r = 0; r < 16; r++) {
            int idx = tid + r * 128;
            int ep =  idx & 3;
            int il = (idx >> 2) & 31;
            int bb =  idx >> 7;
            int gb = bg * 16 + bb;
            float2 uu = *reinterpret_cast<const float2*>(
                u + ((size_t)gb * 1152 + i0 + il) * 8 + 2 * ep);
            float cc;
            if (MODE == 0) cc = 0.01f;
            else cc = c[((size_t)gb * 100 + o) * 1152 + i0 + il];
            cu2_s[idx] = pack2(cc * uu.x, cc * uu.y);
        }
        // build W2_s (transpose): gmem-linear idx = (il*16+dd)*4+ep
        #pragma unroll
        for (int r = 0; r < 16; r++) {
            int idx = tid + r * 128;
            int ep =  idx & 3;
            int dd = (idx >> 2) & 15;
            int il =  idx >> 6;
            float2 ww = *reinterpret_cast<const float2*>(
                Wc + (((size_t)o * 1152 + i0 + il) * 16 + dd) * 8 + 2 * ep);
            W2_s[(il * 4 + ep) * 16 + dd] = pack2(ww.x, ww.y);
        }
        __syncthreads();
        // main: 32 il x 4 ep, per thread: LDS.128 W-pair + LDS.64 cu + 2 ffma2
        #pragma unroll 4
        for (int il = 0; il < 32; il++) {
            {
                ulonglong2 w = *reinterpret_cast<const ulonglong2*>(
                    &W2_s[(il * 4 + 0) * 16 + 2 * dp]);
                ull cu = cu2_s[(bl * 32 + il) * 4 + 0];
                accA0 = ffma2(w.x, cu, accA0);
                accB0 = ffma2(w.y, cu, accB0);
            }
            {
                ulonglong2 w = *reinterpret_cast<const ulonglong2*>(
                    &W2_s[(il * 4 + 1) * 16 + 2 * dp]);
                ull cu = cu2_s[(bl * 32 + il) * 4 + 1];
                accA1 = ffma2(w.x, cu, accA1);
                accB1 = ffma2(w.y, cu, accB1);
            }
            {
                ulonglong2 w = *reinterpret_cast<const ulonglong2*>(
                    &W2_s[(il * 4 + 2) * 16 + 2 * dp]);
                ull cu = cu2_s[(bl * 32 + il) * 4 + 2];
                accA0 = ffma2(w.x, cu, accA0);
                accB0 = ffma2(w.y, cu, accB0);
            }
            {
                ulonglong2 w = *reinterpret_cast<const ulonglong2*>(
                    &W2_s[(il * 4 + 3) * 16 + 2 * dp]);
                ull cu = cu2_s[(bl * 32 + il) * 4 + 3];
                accA1 = ffma2(w.x, cu, accA1);
                accB1 = ffma2(w.y, cu, accB1);
            }
        }
    }

    // s[d0], s[d1]: sum packed e-lanes
    ull accA = add2(accA0, accA1);
    ull accB = add2(accB0, accB1);
    float a_lo, a_hi, b_lo, b_hi;
    unpack2(accA, a_lo, a_hi);
    unpack2(accB, b_lo, b_hi);
    float s0 = a_lo + a_hi;
    float s1 = b_lo + b_hi;
    ss[bl][2 * dp]     = s0;
    ss[bl][2 * dp + 1] = s1;
    __syncthreads();
    float n2 = 0.f;
    #pragma unroll
    for (int q = 0; q < 16; q++) { float t = ss[bl][q]; n2 = fmaf(t, t, n2); }
    float sc = (n2 / (1.f + n2)) * rsqrtf(n2 + 1e-8f);
    float2 vv = make_float2(s0 * sc, s1 * sc);
    *reinterpret_cast<float2*>(v + ((size_t)b * 100 + o) * 16 + 2 * dp) = vv;
}

// ---------------------------------------------------------------------------
// route_blog_gemm<FIRST>: blog[b,o,i] (+)= sum_e u[b,i,e] *
//                                     (sum_d W[o,i,d,e] * v[b,o,d])
// Grid (100 o, 8 bg). Block 256 = 16 b x 16 il (il covers i=il, il+16).
// W chunk in smem as d-pair u64, layout [(dp*8+e)*33 + i] (padded, conflict-
// free main LDS over consecutive i). v held in registers (8 d-pair u64).
// ---------------------------------------------------------------------------
template<bool FIRST>
__global__ void route_blog_gemm(const float* __restrict__ Wc,
                                const float* __restrict__ u,
                                const float* __restrict__ v,
                                float* __restrict__ blog)
{
    __shared__ __align__(16) ull W2_s[8 * 8 * 33];  // 16.9KB

    const int o   = blockIdx.x;
    const int bg  = blockIdx.y;
    const int tid = threadIdx.x;
    const int il  = tid & 15;
    const int bl  = tid >> 4;
    const int b   = bg * 16 + bl;

    // v pairs for this thread's batch
    ull v2[8];
    #pragma unroll
    for (int dp = 0; dp < 8; dp++) {
        float2 vv = *reinterpret_cast<const float2*>(
            v + ((size_t)b * 100 + o) * 16 + 2 * dp);
        v2[dp] = pack2(vv.x, vv.y);
    }

    for (int i0 = 0; i0 < 1152; i0 += 32) {
        __syncthreads();
        // load W chunk as d-pairs: 2048 u64; idx -> (i, dp, e), e fastest
        #pragma unroll
        for (int r = 0; r < 8; r++) {
            int idx = tid + r * 256;
            int e  =  idx & 7;
            int dp = (idx >> 3) & 7;
            int ii =  idx >> 6;
            const float* wp = Wc + (((size_t)o * 1152 + i0 + ii) * 16 + 2 * dp) * 8 + e;
            W2_s[(dp * 8 + e) * 33 + ii] = pack2(wp[0], wp[8]);
        }
        __syncthreads();

        #pragma unroll
        for (int r = 0; r < 2; r++) {
            int i = il + 16 * r;
            const float4* up = reinterpret_cast<const float4*>(
                u + ((size_t)b * 1152 + i0 + i) * 8);
            float4 ua = up[0], ub = up[1];
            float uu[8] = {ua.x, ua.y, ua.z, ua.w, ub.x, ub.y, ub.z, ub.w};
            float dot = 0.f;
            #pragma unroll
            for (int e = 0; e < 8; e++) {
                ull za = 0ull, zb = 0ull;
                #pragma unroll
                for (int dp = 0; dp < 8; dp += 2) {
                    za = ffma2(W2_s[(dp * 8 + e) * 33 + i], v2[dp], za);
                    zb = ffma2(W2_s[((dp + 1) * 8 + e) * 33 + i], v2[dp + 1], zb);
                }
                ull z2 = add2(za, zb);
                float zl, zh;
                unpack2(z2, zl, zh);
                dot = fmaf(uu[e], zl + zh, dot);
            }
            size_t bi = ((size_t)b * 100 + o) * 1152 + i0 + i;
            if (FIRST) blog[bi] = dot;
            else       blog[bi] += dot;
        }
    }
}

// ---------------------------------------------------------------------------
// Softmax over o (100 entries) for each (b, i).
// ---------------------------------------------------------------------------
__global__ void softmax_o_kernel(const float* __restrict__ blog, float* __restrict__ c)
{
    __shared__ float t[100][33];
    int i0 = blockIdx.x * 32, b = blockIdx.y, tid = threadIdx.x;
    for (int idx = tid; idx < 100 * 32; idx += 128) {
        int ii = idx % 32, o = idx / 32;
        t[o][ii] = blog[((size_t)(b * 100 + o)) * 1152 + i0 + ii];
    }
    __syncthreads();
    if (tid < 32) {
        float mx = -1e30f;
        for (int o = 0; o < 100; o++) mx = fmaxf(mx, t[o][tid]);
        float sm = 0.f;
        for (int o = 0; o < 100; o++) {
            float e = expf(t[o][tid] - mx);
            t[o][tid] = e;
            sm += e;
        }
        float inv = 1.f / sm;
        for (int o = 0; o < 100; o++) t[o][tid] *= inv;
    }
    __syncthreads();
    for (int idx = tid; idx < 100 * 32; idx += 128) {
        int ii = idx % 32, o = idx / 32;
        c[((size_t)(b * 100 + o)) * 1152 + i0 + ii] = t[o][ii];
    }
}

// ---------------------------------------------------------------------------
// FC with packed f32x2 (unchanged from passing R6).
// ---------------------------------------------------------------------------
template<bool RELU>
__global__ void fc_kernel(const float* __restrict__ A, const float* __restrict__ Wm,
                          const float* __restrict__ bias, float* __restrict__ C,
                          int K, int N)
{
    __shared__ __align__(16) ull As2[16][66];
    __shared__ __align__(16) float Bs[16][68];
    int tid = threadIdx.x;
    int n0 = blockIdx.x * 64, m0 = blockIdx.y * 64;
    int tx = tid % 16, ty = tid / 16;
    ull acc2[4][2];
    #pragma unroll
    for (int i = 0; i < 4; i++)
        #pragma unroll
        for (int j = 0; j < 2; j++) acc2[i][j] = 0ull;

    for (int k0 = 0; k0 < K; k0 += 16) {
        #pragma unroll
        for (int rep = 0; rep < 4; rep++) {
            int idx = tid + rep * 256;
            int b_l = idx / 16, k_l = idx % 16;
            float a = A[(size_t)(m0 + b_l) * K + k0 + k_l];
            As2[k_l][b_l] = pack2(a, a);
        }
        #pragma unroll
        for (int rep = 0; rep < 4; rep++) {
            int idx = tid + rep * 256;
            int k_l = idx / 64, n_l = idx % 64;
            int n = n0 + n_l;
            Bs[k_l][n_l] = (n < N) ? Wm[(size_t)(k0 + k_l) * N + n] : 0.f;
        }
        __syncthreads();
        #pragma unroll
        for (int k = 0; k < 16; k++) {
            const ulonglong2* bp = reinterpret_cast<const ulonglong2*>(&Bs[k][tx * 4]);
            ulonglong2 bb = bp[0];
            ull a0 = As2[k][ty * 4 + 0];
            ull a1 = As2[k][ty * 4 + 1];
            ull a2 = As2[k][ty * 4 + 2];
            ull a3 = As2[k][ty * 4 + 3];
            acc2[0][0] = ffma2(a0, bb.x, acc2[0][0]);
            acc2[0][1] = ffma2(a0, bb.y, acc2[0][1]);
            acc2[1][0] = ffma2(a1, bb.x, acc2[1][0]);
            acc2[1][1] = ffma2(a1, bb.y, acc2[1][1]);
            acc2[2][0] = ffma2(a2, bb.x, acc2[2][0]);
            acc2[2][1] = ffma2(a2, bb.y, acc2[2][1]);
            acc2[3][0] = ffma2(a3, bb.x, acc2[3][0]);
            acc2[3][1] = ffma2(a3, bb.y, acc2[3][1]);
        }
        __syncthreads();
    }
    #pragma unroll
    for (int i = 0; i < 4; i++) {
        int m = m0 + ty * 4 + i;
        #pragma unroll
        for (int j = 0; j < 2; j++) {
            float lo, hi;
            unpack2(acc2[i][j], lo, hi);
            int n_lo = n0 + tx * 4 + 2 * j;
            int n_hi = n_lo + 1;
            if (n_lo < N) {
                float val = lo + bias[n_lo];
                if (RELU) val = fmaxf(val, 0.f);
                C[(size_t)m * N + n_lo] = val;
            }
            if (n_hi < N) {
                float val = hi + bias[n_hi];
                if (RELU) val = fmaxf(val, 0.f);
                C[(size_t)m * N + n_hi] = val;
            }
        }
    }
}

// ---------------------------------------------------------------------------
// launch
// ---------------------------------------------------------------------------
extern "C" void kernel_launch(void* const* d_in, const int* in_sizes, int n_in,
                              void* d_out, int out_size)
{
    const float* x     = (const float*)d_in[0];
    const float* cw1   = (const float*)d_in[1];
    const float* cb1   = (const float*)d_in[2];
    const float* cw2   = (const float*)d_in[3];
    const float* cb2   = (const float*)d_in[4];
    const float* cw3   = (const float*)d_in[5];
    const float* cb3   = (const float*)d_in[6];
    const float* pw    = (const float*)d_in[7];
    const float* pb    = (const float*)d_in[8];
    const float* Wcaps = (const float*)d_in[9];
    const float* fw1   = (const float*)d_in[10];
    const float* fb1   = (const float*)d_in[11];
    const float* fw2   = (const float*)d_in[12];
    const float* fb2   = (const float*)d_in[13];
    const float* fw3   = (const float*)d_in[14];
    const float* fb3   = (const float*)d_in[15];

    void* sp = nullptr;
    cudaGetSymbolAddress(&sp, g_scratch);
    float* S    = (float*)sp;

    float* buf1 = S + O_BUF1;
    float* buf2 = S + O_BUF2;
    float* buf3 = S + O_BUF3;
    float* buf4 = S + O_BUF4;
    float* buf5 = S + O_BUF5;
    float* buf6 = S + O_BUF6;
    float* u    = S + O_U;
    float* blog = S + O_BLOG;
    float* cbuf = S + O_C;
    float* v    = S + O_V;
    float* f1   = S + O_F1;
    float* f2   = S + O_F2;
    float* outp = (float*)d_out;

    // conv backbone
    conv3x3_kernel<3, 32, 32, 96, 32, 32, 1, 3, 4, 1, true>
        <<<dim3(12, BATCH), 256>>>(x, cw1, cb1, buf1);
    maxpool_kernel<96, 32><<<(BATCH * 96 * 16 * 16 + 255) / 256, 256>>>(buf1, buf2);
    conv3x3_kernel<96, 16, 16, 256, 16, 16, 1, 8, 4, 4, true>
        <<<dim3(8, BATCH), 256>>>(buf2, cw2, cb2, buf3);
    maxpool_kernel<256, 16><<<(BATCH * 256 * 8 * 8 + 255) / 256, 256>>>(buf3, buf4);
    conv3x3_kernel<256, 8, 8, 384, 8, 8, 1, 8, 4, 16, true>
        <<<dim3(3, BATCH), 256>>>(buf4, cw3, cb3, buf5);
    conv3x3_kernel<384, 8, 8, 256, 6, 6, 0, 8, 6, 16, false>
        <<<dim3(2, BATCH), 96>>>(buf5, pw, pb, buf6);
    squash_u_kernel<<<(BATCH * 1152 + 255) / 256, 256>>>(buf6, u);

    // routing via direct W-contraction (no xhat materialization, pure fp32)
    route_s_gemm<0><<<dim3(100, 8), 128>>>(Wcaps, u, cbuf, v);
    route_blog_gemm<true><<<dim3(100, 8), 256>>>(Wcaps, u, v, blog);
    softmax_o_kernel<<<dim3(36, BATCH), 128>>>(blog, cbuf);
    route_s_gemm<1><<<dim3(100, 8), 128>>>(Wcaps, u, cbuf, v);
    route_blog_gemm<false><<<dim3(100, 8), 256>>>(Wcaps, u, v, blog);
    softmax_o_kernel<<<dim3(36, BATCH), 128>>>(blog, cbuf);
    route_s_gemm<1><<<dim3(100, 8), 128>>>(Wcaps, u, cbuf, v);

    // FC head
    fc_kernel<true><<<dim3(64, 2), 256>>>(v, fw1, fb1, f1, 1600, 4096);
    fc_kernel<true><<<dim3(64, 2), 256>>>(f1, fw2, fb2, f2, 4096, 4096);
    fc_kernel<false><<<dim3(2, 2), 256>>>(f2, fw3, fb3, outp, 4096, 100);

    (void)in_sizes; (void)n_in; (void)out_size;
}

// round 9
// speedup vs baseline: 2.5837x; 2.5837x over previous
#include <cuda_runtime.h>
#include <cuda_fp16.h>
#include <cstddef>
#include <cstdint>
#include <math.h>

#define BATCH 128

typedef unsigned long long ull;

// ---------------------------------------------------------------------------
// f32x2 packed helpers (sm_103a): 2 fp32 ops per issue slot, exact fp32.
// ---------------------------------------------------------------------------
__device__ __forceinline__ ull pack2(float lo, float hi) {
    ull r;
    asm("mov.b64 %0, {%1, %2};" : "=l"(r) : "f"(lo), "f"(hi));
    return r;
}
__device__ __forceinline__ void unpack2(ull v, float& lo, float& hi) {
    asm("mov.b64 {%0, %1}, %2;" : "=f"(lo), "=f"(hi) : "l"(v));
}
__device__ __forceinline__ ull ffma2(ull a, ull b, ull c) {
    ull d;
    asm("fma.rn.f32x2 %0, %1, %2, %3;" : "=l"(d) : "l"(a), "l"(b), "l"(c));
    return d;
}

// ---------------------------------------------------------------------------
// Scratch (no allocations allowed): fp32 scratch + fp16 xhat.
// Padded layouts: buf2p [96,18,18], buf4p [256,10,10], buf5p [384,10,10].
// ---------------------------------------------------------------------------
constexpr size_t N_BUF1 = (size_t)BATCH * 96 * 32 * 32;   // conv1 out (unpadded)
constexpr size_t N_BUF2 = (size_t)BATCH * 96 * 18 * 18;   // pool1 (padded)
constexpr size_t N_BUF3 = (size_t)BATCH * 256 * 16 * 16;  // conv2 out (unpadded)
constexpr size_t N_BUF4 = (size_t)BATCH * 256 * 10 * 10;  // pool2 (padded)
constexpr size_t N_BUF5 = (size_t)BATCH * 384 * 10 * 10;  // conv3 out (padded)
constexpr size_t N_BUF6 = (size_t)BATCH * 256 * 6 * 6;    // pcaps out
constexpr size_t N_U    = (size_t)BATCH * 1152 * 8;
constexpr size_t N_BLOG = (size_t)BATCH * 100 * 1152;
constexpr size_t N_C    = (size_t)BATCH * 100 * 1152;
constexpr size_t N_V    = (size_t)BATCH * 100 * 16;
constexpr size_t N_F1   = (size_t)BATCH * 4096;
constexpr size_t N_F2   = (size_t)BATCH * 4096;
constexpr size_t N_XHAT = (size_t)BATCH * 100 * 1152 * 16;

constexpr size_t O_BUF1 = 0;
constexpr size_t O_BUF2 = O_BUF1 + N_BUF1;
constexpr size_t O_BUF3 = O_BUF2 + N_BUF2;
constexpr size_t O_BUF4 = O_BUF3 + N_BUF3;
constexpr size_t O_BUF5 = O_BUF4 + N_BUF4;
constexpr size_t O_BUF6 = O_BUF5 + N_BUF5;
constexpr size_t O_U    = O_BUF6 + N_BUF6;
constexpr size_t O_BLOG = O_U + N_U;
constexpr size_t O_C    = O_BLOG + N_BLOG;
constexpr size_t O_V    = O_C + N_C;
constexpr size_t O_F1   = O_V + N_V;
constexpr size_t O_F2   = O_F1 + N_F1;
constexpr size_t N_TOTAL = O_F2 + N_F2;

__device__ __align__(16) float g_scratch[N_TOTAL];
__device__ __align__(16) __half g_xhat[N_XHAT];

// ---------------------------------------------------------------------------
// conv1 only: guarded-load direct conv (R5 version, small CIN=3).
// ---------------------------------------------------------------------------
template<int CIN, int HIN, int WIN, int COUT, int HOUT, int WOUT, int PAD,
         int ICC, int PPT, int NOCSUB, bool RELU>
__global__ void conv3x3_kernel(const float* __restrict__ in,
                               const float* __restrict__ wt,
                               const float* __restrict__ bias,
                               float* __restrict__ out)
{
    constexpr int NPG = (HOUT * WOUT) / PPT;
    constexpr int NT  = NPG * NOCSUB;
    constexpr int OCB = NOCSUB * 8;
    constexpr int HT  = HIN + 2 * PAD;
    constexpr int WT  = WIN + 2 * PAD;
    constexpr int WTP = WT + 1;

    __shared__ __align__(16) ull in_s2[ICC * HT * WTP];
    __shared__ __align__(16) float w_s[ICC * 9 * OCB];

    const int tid   = threadIdx.x;
    const int ocblk = blockIdx.x;
    const int b     = blockIdx.y;

    const int pg   = tid % NPG;
    const int ocs  = tid / NPG;
    const int row  = pg / (WOUT / PPT);
    const int col0 = (pg % (WOUT / PPT)) * PPT;
    const int oc0  = ocblk * OCB + ocs * 8;

    ull acc2[PPT][4];
    #pragma unroll
    for (int j4 = 0; j4 < 4; j4++) {
        ull bp = pack2(bias[oc0 + 2 * j4], bias[oc0 + 2 * j4 + 1]);
        #pragma unroll
        for (int p = 0; p < PPT; p++) acc2[p][j4] = bp;
    }

    for (int ic0 = 0; ic0 < CIN; ic0 += ICC) {
        __syncthreads();
        for (int idx = tid; idx < ICC * HT * WT; idx += NT) {
            int x  = idx % WT;
            int y  = (idx / WT) % HT;
            int ic = idx / (WT * HT);
            int gy = y - PAD, gx = x - PAD;
            float v = 0.f;
            if (gy >= 0 && gy < HIN && gx >= 0 && gx < WIN)
                v = in[((size_t)(b * CIN + ic0 + ic) * HIN + gy) * WIN + gx];
            in_s2[(ic * HT + y) * WTP + x] = pack2(v, v);
        }
        for (int idx = tid; idx < ICC * 9 * OCB; idx += NT) {
            int oc_l = idx % OCB;
            int tap  = (idx / OCB) % 9;
            int ic   = idx / (OCB * 9);
            w_s[(ic * 9 + tap) * OCB + oc_l] =
                wt[((size_t)(ocblk * OCB + oc_l) * CIN + ic0 + ic) * 9 + tap];
        }
        __syncthreads();

        #pragma unroll
        for (int ic = 0; ic < ICC; ic++) {
            #pragma unroll
            for (int ky = 0; ky < 3; ky++) {
                ull xq[PPT + 2];
                #pragma unroll
                for (int q = 0; q < PPT + 2; q++)
                    xq[q] = in_s2[(ic * HT + row + ky) * WTP + col0 + q];
                #pragma unroll
                for (int kx = 0; kx < 3; kx++) {
                    const ulonglong2* wp = reinterpret_cast<const ulonglong2*>(
                        &w_s[(ic * 9 + ky * 3 + kx) * OCB + ocs * 8]);
                    ulonglong2 wA = wp[0];
                    ulonglong2 wB = wp[1];
                    #pragma unroll
                    for (int p = 0; p < PPT; p++) {
                        ull xv = xq[p + kx];
                        acc2[p][0] = ffma2(xv, wA.x, acc2[p][0]);
                        acc2[p][1] = ffma2(xv, wA.y, acc2[p][1]);
                        acc2[p][2] = ffma2(xv, wB.x, acc2[p][2]);
                        acc2[p][3] = ffma2(xv, wB.y, acc2[p][3]);
                    }
                }
            }
        }
    }

    #pragma unroll
    for (int j4 = 0; j4 < 4; j4++) {
        #pragma unroll
        for (int p = 0; p < PPT; p++) {
            float lo, hi;
            unpack2(acc2[p][j4], lo, hi);
            if (RELU) { lo = fmaxf(lo, 0.f); hi = fmaxf(hi, 0.f); }
            size_t ob = ((size_t)(b * COUT + oc0 + 2 * j4) * HOUT + row) * WOUT + col0 + p;
            out[ob] = lo;
            out[ob + (size_t)HOUT * WOUT] = hi;
        }
    }
}

// ---------------------------------------------------------------------------
// Padded-input conv: input layout [CIN, HIN+2, WIN+2] with zero borders.
// Tile load = guard-free flat float4 copy, register-prefetch pipelined.
// IOFF: extra offset into padded layout (pcaps: conv pad 0 over padded buf).
// OUTPAD: write output into padded layout (conv3 feeding pcaps).
// ---------------------------------------------------------------------------
template<int CIN, int HIN, int WIN, int COUT, int HOUT, int WOUT,
         int ICC, int PPT, int NOCSUB, bool RELU, int IOFF, int OUTPAD>
__global__ void conv3x3p_kernel(const float* __restrict__ in,
                                const float* __restrict__ wt,
                                const float* __restrict__ bias,
                                float* __restrict__ out)
{
    constexpr int NPG = (HOUT * WOUT) / PPT;
    constexpr int NT  = NPG * NOCSUB;
    constexpr int OCB = NOCSUB * 8;
    constexpr int LH  = HIN + 2, LW = WIN + 2;
    constexpr int F   = ICC * LH * LW;          // floats per chunk
    constexpr int F4  = F / 4;
    constexpr int FI4 = (F4 + NT - 1) / NT;
    constexpr int CPG = WOUT / PPT;
    constexpr int NCH = CIN / ICC;
    constexpr int OH  = HOUT + 2 * OUTPAD, OW = WOUT + 2 * OUTPAD;

    __shared__ __align__(16) ull in_s2[F];
    __shared__ __align__(16) float w_s[ICC * 9 * OCB];

    const int tid   = threadIdx.x;
    const int ocblk = blockIdx.x;
    const int b     = blockIdx.y;

    const int pg   = tid % NPG;
    const int ocs  = tid / NPG;
    const int row  = pg / CPG;
    const int col0 = (pg % CPG) * PPT;
    const int oc0  = ocblk * OCB + ocs * 8;

    ull acc2[PPT][4];
    #pragma unroll
    for (int j4 = 0; j4 < 4; j4++) {
        ull bp = pack2(bias[oc0 + 2 * j4], bias[oc0 + 2 * j4 + 1]);
        #pragma unroll
        for (int p = 0; p < PPT; p++) acc2[p][j4] = bp;
    }

    float4 tbuf[FI4];
    // prefetch chunk 0
    {
        const float4* src = reinterpret_cast<const float4*>(
            in + (size_t)(b * CIN) * LH * LW);
        #pragma unroll
        for (int r = 0; r < FI4; r++) {
            int t = tid + r * NT;
            if (t < F4) tbuf[r] = src[t];
        }
    }

    for (int c0 = 0; c0 < NCH; c0++) {
        const int ic0 = c0 * ICC;
        __syncthreads();
        // store tile (duplicated pack) + weights
        #pragma unroll
        for (int r = 0; r < FI4; r++) {
            int t = tid + r * NT;
            if (t < F4) {
                float4 v = tbuf[r];
                in_s2[4 * t + 0] = pack2(v.x, v.x);
                in_s2[4 * t + 1] = pack2(v.y, v.y);
                in_s2[4 * t + 2] = pack2(v.z, v.z);
                in_s2[4 * t + 3] = pack2(v.w, v.w);
            }
        }
        for (int idx = tid; idx < ICC * 9 * OCB; idx += NT) {
            int oc_l = idx % OCB;
            int tap  = (idx / OCB) % 9;
            int ic   = idx / (OCB * 9);
            w_s[(ic * 9 + tap) * OCB + oc_l] =
                wt[((size_t)(ocblk * OCB + oc_l) * CIN + ic0 + ic) * 9 + tap];
        }
        __syncthreads();
        // prefetch next chunk (hidden behind compute)
        if (c0 + 1 < NCH) {
            const float4* src = reinterpret_cast<const float4*>(
                in + (size_t)(b * CIN + ic0 + ICC) * LH * LW);
            #pragma unroll
            for (int r = 0; r < FI4; r++) {
                int t = tid + r * NT;
                if (t < F4) tbuf[r] = src[t];
            }
        }
        // compute
        #pragma unroll
        for (int ic = 0; ic < ICC; ic++) {
            #pragma unroll
            for (int ky = 0; ky < 3; ky++) {
                ull xq[PPT + 2];
                int base = (ic * LH + row + IOFF + ky) * LW + col0 + IOFF;
                #pragma unroll
                for (int q = 0; q < PPT + 2; q++) xq[q] = in_s2[base + q];
                #pragma unroll
                for (int kx = 0; kx < 3; kx++) {
                    const ulonglong2* wp = reinterpret_cast<const ulonglong2*>(
                        &w_s[(ic * 9 + ky * 3 + kx) * OCB + ocs * 8]);
                    ulonglong2 wA = wp[0];
                    ulonglong2 wB = wp[1];
                    #pragma unroll
                    for (int p = 0; p < PPT; p++) {
                        ull xv = xq[p + kx];
                        acc2[p][0] = ffma2(xv, wA.x, acc2[p][0]);
                        acc2[p][1] = ffma2(xv, wA.y, acc2[p][1]);
                        acc2[p][2] = ffma2(xv, wB.x, acc2[p][2]);
                        acc2[p][3] = ffma2(xv, wB.y, acc2[p][3]);
                    }
                }
            }
        }
    }

    #pragma unroll
    for (int j4 = 0; j4 < 4; j4++) {
        #pragma unroll
        for (int p = 0; p < PPT; p++) {
            float lo, hi;
            unpack2(acc2[p][j4], lo, hi);
            if (RELU) { lo = fmaxf(lo, 0.f); hi = fmaxf(hi, 0.f); }
            size_t ob = ((size_t)(b * COUT + oc0 + 2 * j4) * OH + row + OUTPAD) * OW
                        + col0 + p + OUTPAD;
            out[ob] = lo;
            out[ob + (size_t)OH * OW] = hi;
        }
    }
}

// ---------------------------------------------------------------------------
// MaxPool 3x3 stride 2 pad 1; optionally writes padded output layout.
// ---------------------------------------------------------------------------
template<int C, int HIN, int OUTPAD>
__global__ void maxpool_kernel(const float* __restrict__ in, float* __restrict__ out)
{
    constexpr int HO = HIN / 2;
    int idx = blockIdx.x * blockDim.x + threadIdx.x;
    if (idx >= BATCH * C * HO * HO) return;
    int ox = idx % HO;
    int oy = (idx / HO) % HO;
    int c  = (idx / (HO * HO)) % C;
    int b  = idx / (HO * HO * C);
    const float* p = in + ((size_t)(b * C + c)) * HIN * HIN;
    float m = -1e30f;
    #pragma unroll
    for (int dy = 0; dy < 3; dy++) {
        int y = 2 * oy - 1 + dy;
        if (y < 0 || y >= HIN) continue;
        #pragma unroll
        for (int dx = 0; dx < 3; dx++) {
            int x = 2 * ox - 1 + dx;
            if (x < 0 || x >= HIN) continue;
            m = fmaxf(m, p[y * HIN + x]);
        }
    }
    if (OUTPAD) {
        constexpr int HOP = HO + 2;
        out[((size_t)(b * C + c) * HOP + oy + 1) * HOP + ox + 1] = m;
    } else {
        out[idx] = m;
    }
}

// ---------------------------------------------------------------------------
// Squash primarycaps: p flat [B,9216] -> u [B,1152,8]
// ---------------------------------------------------------------------------
__global__ void squash_u_kernel(const float* __restrict__ p, float* __restrict__ u)
{
    int cap = blockIdx.x * blockDim.x + threadIdx.x;
    if (cap >= BATCH * 1152) return;
    const float4* s = reinterpret_cast<const float4*>(p + (size_t)cap * 8);
    float4 a = s[0], b4 = s[1];
    float n2 = a.x * a.x + a.y * a.y + a.z * a.z + a.w * a.w +
               b4.x * b4.x + b4.y * b4.y + b4.z * b4.z + b4.w * b4.w;
    float sc = (n2 / (1.f + n2)) * rsqrtf(n2 + 1e-8f);
    float4* o = reinterpret_cast<float4*>(u + (size_t)cap * 8);
    o[0] = make_float4(a.x * sc, a.y * sc, a.z * sc, a.w * sc);
    o[1] = make_float4(b4.x * sc, b4.y * sc, b4.z * sc, b4.w * sc);
}

// ---------------------------------------------------------------------------
// x_hat[b,o,i,d] = sum_e W[o,i,d,e] * u[b,i,e], stored fp16.
// ---------------------------------------------------------------------------
__global__ void xhat16_kernel(const float* __restrict__ Wc,
                              const float* __restrict__ u,
                              __half* __restrict__ xh)
{
    __shared__ float u_s[256];
    const int o  = blockIdx.y;
    const int i0 = blockIdx.x * 32;
    const int tid = threadIdx.x;
    const int il  = tid >> 3;
    const int dp  = tid & 7;

    const float4* wg4 = reinterpret_cast<const float4*>(
        Wc + (((size_t)o * 1152 + i0 + il) * 16 + dp * 2) * 8);
    float4 w0 = wg4[0], w1 = wg4[1], w2 = wg4[2], w3 = wg4[3];
    float wA[8] = {w0.x, w0.y, w0.z, w0.w, w1.x, w1.y, w1.z, w1.w};
    float wB[8] = {w2.x, w2.y, w2.z, w2.w, w3.x, w3.y, w3.z, w3.w};

    for (int b = 0; b < BATCH; b++) {
        __syncthreads();
        u_s[tid] = u[((size_t)b * 1152 + i0) * 8 + tid];
        __syncthreads();
        const float* ur = &u_s[il * 8];
        float a0 = 0.f, a1 = 0.f;
        #pragma unroll
        for (int e = 0; e < 8; e++) {
            a0 = fmaf(wA[e], ur[e], a0);
            a1 = fmaf(wB[e], ur[e], a1);
        }
        *reinterpret_cast<__half2*>(
            xh + (((size_t)b * 100 + o) * 1152 + i0 + il) * 16 + dp * 2) =
            __floats2half2_rn(a0, a1);
    }
}

// ---------------------------------------------------------------------------
// Fused routing iteration (smem-only squash reduction; all barriers uniform).
// ---------------------------------------------------------------------------
template<int MODE>
__global__ void route_fused_kernel(const __half* __restrict__ xhat,
                                   const float* __restrict__ c,
                                   float* __restrict__ blog,
                                   float* __restrict__ v)
{
    __shared__ __align__(16) __half xs[1152 * 16];
    __shared__ float cs[1152];
    __shared__ float red[256];
    __shared__ float vs[16];

    const int o = blockIdx.x, b = blockIdx.y, tid = threadIdx.x;
    const size_t base = (size_t)(b * 100 + o);

    const float4* xg = reinterpret_cast<const float4*>(xhat + base * 1152 * 16);
    float4* xs4 = reinterpret_cast<float4*>(xs);
    #pragma unroll
    for (int k = 0; k < 9; k++) xs4[tid + k * 256] = xg[tid + k * 256];

    if (MODE != 0) {
        const float* cg = c + base * 1152;
        for (int i = tid; i < 1152; i += 256) cs[i] = cg[i];
    }
    __syncthreads();

    const int d = tid & 15, ig = tid >> 4;
    float acc = 0.f;
    for (int i = ig; i < 1152; i += 16) {
        float x = __half2float(xs[i * 16 + d]);
        if (MODE == 0) acc += x;
        else           acc = fmaf(cs[i], x, acc);
    }
    red[tid] = acc;
    __syncthreads();
    #pragma unroll
    for (int st = 128; st >= 16; st >>= 1) {
        if (tid < st) red[tid] += red[tid + st];
        __syncthreads();
    }
    if (tid < 16) {
        float s = red[tid];
        if (MODE == 0) s *= 0.01f;
        red[tid] = s;
    }
    __syncthreads();
    if (tid < 16) {
        float n2 = 0.f;
        #pragma unroll
        for (int q = 0; q < 16; q++) n2 += red[q] * red[q];
        float sc = (n2 / (1.f + n2)) * rsqrtf(n2 + 1e-8f);
        float vv = red[tid] * sc;
        vs[tid] = vv;
        if (MODE == 2) v[base * 16 + tid] = vv;
    }
    if (MODE == 2) return;
    __syncthreads();

    float* bl = blog + base * 1152;
    for (int i = tid; i < 1152; i += 256) {
        const float4* xp = reinterpret_cast<const float4*>(xs + i * 16);
        float4 p0 = xp[0], p1 = xp[1];
        const __half2* h0 = reinterpret_cast<const __half2*>(&p0);
        const __half2* h1 = reinterpret_cast<const __half2*>(&p1);
        float dot = 0.f;
        #pragma unroll
        for (int q = 0; q < 4; q++) {
            float2 f = __half22float2(h0[q]);
            dot = fmaf(f.x, vs[q * 2 + 0], dot);
            dot = fmaf(f.y, vs[q * 2 + 1], dot);
        }
        #pragma unroll
        for (int q = 0; q < 4; q++) {
            float2 f = __half22float2(h1[q]);
            dot = fmaf(f.x, vs[8 + q * 2 + 0], dot);
            dot = fmaf(f.y, vs[8 + q * 2 + 1], dot);
        }
        if (MODE == 0) bl[i] = dot;
        else           bl[i] += dot;
    }
}

// ---------------------------------------------------------------------------
// Softmax over o (100 entries) for each (b, i).
// ---------------------------------------------------------------------------
__global__ void softmax_o_kernel(const float* __restrict__ blog, float* __restrict__ c)
{
    __shared__ float t[100][33];
    int i0 = blockIdx.x * 32, b = blockIdx.y, tid = threadIdx.x;
    for (int idx = tid; idx < 100 * 32; idx += 128) {
        int ii = idx % 32, o = idx / 32;
        t[o][ii] = blog[((size_t)(b * 100 + o)) * 1152 + i0 + ii];
    }
    __syncthreads();
    if (tid < 32) {
        float mx = -1e30f;
        for (int o = 0; o < 100; o++) mx = fmaxf(mx, t[o][tid]);
        float sm = 0.f;
        for (int o = 0; o < 100; o++) {
            float e = expf(t[o][tid] - mx);
            t[o][tid] = e;
            sm += e;
        }
        float inv = 1.f / sm;
        for (int o = 0; o < 100; o++) t[o][tid] *= inv;
    }
    __syncthreads();
    for (int idx = tid; idx < 100 * 32; idx += 128) {
        int ii = idx % 32, o = idx / 32;
        c[((size_t)(b * 100 + o)) * 1152 + i0 + ii] = t[o][ii];
    }
}

// ---------------------------------------------------------------------------
// FC with packed f32x2 (unchanged from R5).
// ---------------------------------------------------------------------------
template<bool RELU>
__global__ void fc_kernel(const float* __restrict__ A, const float* __restrict__ Wm,
                          const float* __restrict__ bias, float* __restrict__ C,
                          int K, int N)
{
    __shared__ __align__(16) ull As2[16][66];
    __shared__ __align__(16) float Bs[16][68];
    int tid = threadIdx.x;
    int n0 = blockIdx.x * 64, m0 = blockIdx.y * 64;
    int tx = tid % 16, ty = tid / 16;
    ull acc2[4][2];
    #pragma unroll
    for (int i = 0; i < 4; i++)
        #pragma unroll
        for (int j = 0; j < 2; j++) acc2[i][j] = 0ull;

    for (int k0 = 0; k0 < K; k0 += 16) {
        #pragma unroll
        for (int rep = 0; rep < 4; rep++) {
            int idx = tid + rep * 256;
            int b_l = idx / 16, k_l = idx % 16;
            float a = A[(size_t)(m0 + b_l) * K + k0 + k_l];
            As2[k_l][b_l] = pack2(a, a);
        }
        #pragma unroll
        for (int rep = 0; rep < 4; rep++) {
            int idx = tid + rep * 256;
            int k_l = idx / 64, n_l = idx % 64;
            int n = n0 + n_l;
            Bs[k_l][n_l] = (n < N) ? Wm[(size_t)(k0 + k_l) * N + n] : 0.f;
        }
        __syncthreads();
        #pragma unroll
        for (int k = 0; k < 16; k++) {
            const ulonglong2* bp = reinterpret_cast<const ulonglong2*>(&Bs[k][tx * 4]);
            ulonglong2 bb = bp[0];
            ull a0 = As2[k][ty * 4 + 0];
            ull a1 = As2[k][ty * 4 + 1];
            ull a2 = As2[k][ty * 4 + 2];
            ull a3 = As2[k][ty * 4 + 3];
            acc2[0][0] = ffma2(a0, bb.x, acc2[0][0]);
            acc2[0][1] = ffma2(a0, bb.y, acc2[0][1]);
            acc2[1][0] = ffma2(a1, bb.x, acc2[1][0]);
            acc2[1][1] = ffma2(a1, bb.y, acc2[1][1]);
            acc2[2][0] = ffma2(a2, bb.x, acc2[2][0]);
            acc2[2][1] = ffma2(a2, bb.y, acc2[2][1]);
            acc2[3][0] = ffma2(a3, bb.x, acc2[3][0]);
            acc2[3][1] = ffma2(a3, bb.y, acc2[3][1]);
        }
        __syncthreads();
    }
    #pragma unroll
    for (int i = 0; i < 4; i++) {
        int m = m0 + ty * 4 + i;
        #pragma unroll
        for (int j = 0; j < 2; j++) {
            float lo, hi;
            unpack2(acc2[i][j], lo, hi);
            int n_lo = n0 + tx * 4 + 2 * j;
            int n_hi = n_lo + 1;
            if (n_lo < N) {
                float val = lo + bias[n_lo];
                if (RELU) val = fmaxf(val, 0.f);
                C[(size_t)m * N + n_lo] = val;
            }
            if (n_hi < N) {
                float val = hi + bias[n_hi];
                if (RELU) val = fmaxf(val, 0.f);
                C[(size_t)m * N + n_hi] = val;
            }
        }
    }
}

// ---------------------------------------------------------------------------
// launch
// ---------------------------------------------------------------------------
extern "C" void kernel_launch(void* const* d_in, const int* in_sizes, int n_in,
                              void* d_out, int out_size)
{
    const float* x     = (const float*)d_in[0];
    const float* cw1   = (const float*)d_in[1];
    const float* cb1   = (const float*)d_in[2];
    const float* cw2   = (const float*)d_in[3];
    const float* cb2   = (const float*)d_in[4];
    const float* cw3   = (const float*)d_in[5];
    const float* cb3   = (const float*)d_in[6];
    const float* pw    = (const float*)d_in[7];
    const float* pb    = (const float*)d_in[8];
    const float* Wcaps = (const float*)d_in[9];
    const float* fw1   = (const float*)d_in[10];
    const float* fb1   = (const float*)d_in[11];
    const float* fw2   = (const float*)d_in[12];
    const float* fb2   = (const float*)d_in[13];
    const float* fw3   = (const float*)d_in[14];
    const float* fb3   = (const float*)d_in[15];

    void* sp = nullptr;
    cudaGetSymbolAddress(&sp, g_scratch);
    float* S = (float*)sp;
    void* xp = nullptr;
    cudaGetSymbolAddress(&xp, g_xhat);
    __half* xhat = (__half*)xp;

    float* buf1 = S + O_BUF1;
    float* buf2 = S + O_BUF2;   // padded [96,18,18]
    float* buf3 = S + O_BUF3;
    float* buf4 = S + O_BUF4;   // padded [256,10,10]
    float* buf5 = S + O_BUF5;   // padded [384,10,10]
    float* buf6 = S + O_BUF6;
    float* u    = S + O_U;
    float* blog = S + O_BLOG;
    float* cbuf = S + O_C;
    float* v    = S + O_V;
    float* f1   = S + O_F1;
    float* f2   = S + O_F2;
    float* outp = (float*)d_out;

    // zero padded buffers (borders must be 0 every call)
    cudaMemsetAsync(buf2, 0, N_BUF2 * sizeof(float));
    cudaMemsetAsync(buf4, 0, N_BUF4 * sizeof(float));
    cudaMemsetAsync(buf5, 0, N_BUF5 * sizeof(float));

    // conv backbone
    conv3x3_kernel<3, 32, 32, 96, 32, 32, 1, 3, 4, 1, true>
        <<<dim3(12, BATCH), 256>>>(x, cw1, cb1, buf1);
    maxpool_kernel<96, 32, 1><<<(BATCH * 96 * 16 * 16 + 255) / 256, 256>>>(buf1, buf2);
    conv3x3p_kernel<96, 16, 16, 256, 16, 16, 8, 4, 4, true, 0, 0>
        <<<dim3(8, BATCH), 256>>>(buf2, cw2, cb2, buf3);
    maxpool_kernel<256, 16, 1><<<(BATCH * 256 * 8 * 8 + 255) / 256, 256>>>(buf3, buf4);
    conv3x3p_kernel<256, 8, 8, 384, 8, 8, 8, 4, 16, true, 0, 1>
        <<<dim3(3, BATCH), 256>>>(buf4, cw3, cb3, buf5);
    conv3x3p_kernel<384, 8, 8, 256, 6, 6, 8, 3, 16, false, 1, 0>
        <<<dim3(2, BATCH), 192>>>(buf5, pw, pb, buf6);
    squash_u_kernel<<<(BATCH * 1152 + 255) / 256, 256>>>(buf6, u);

    // xhat (fp16)
    xhat16_kernel<<<dim3(36, 100), 256>>>(Wcaps, u, xhat);

    // routing: 3 fused iterations, softmax between
    route_fused_kernel<0><<<dim3(100, BATCH), 256>>>(xhat, cbuf, blog, v);
    softmax_o_kernel<<<dim3(36, BATCH), 128>>>(blog, cbuf);
    route_fused_kernel<1><<<dim3(100, BATCH), 256>>>(xhat, cbuf, blog, v);
    softmax_o_kernel<<<dim3(36, BATCH), 128>>>(blog, cbuf);
    route_fused_kernel<2><<<dim3(100, BATCH), 256>>>(xhat, cbuf, blog, v);

    // FC head
    fc_kernel<true><<<dim3(64, 2), 256>>>(v, fw1, fb1, f1, 1600, 4096);
    fc_kernel<true><<<dim3(64, 2), 256>>>(f1, fw2, fb2, f2, 4096, 4096);
    fc_kernel<false><<<dim3(2, 2), 256>>>(f2, fw3, fb3, outp, 4096, 100);

    (void)in_sizes; (void)n_in; (void)out_size;
}

// round 11
// speedup vs baseline: 3.3509x; 1.2969x over previous
#include <cuda_runtime.h>
#include <cuda_fp16.h>
#include <mma.h>
#include <cstddef>
#include <cstdint>
#include <math.h>

using namespace nvcuda;

#define BATCH 128

typedef unsigned long long ull;

// ---------------------------------------------------------------------------
// f32x2 packed helpers (kept for conv1 / FC from the passing R9 code).
// ---------------------------------------------------------------------------
__device__ __forceinline__ ull pack2(float lo, float hi) {
    ull r;
    asm("mov.b64 %0, {%1, %2};" : "=l"(r) : "f"(lo), "f"(hi));
    return r;
}
__device__ __forceinline__ void unpack2(ull v, float& lo, float& hi) {
    asm("mov.b64 {%0, %1}, %2;" : "=f"(lo), "=f"(hi) : "l"(v));
}
__device__ __forceinline__ ull ffma2(ull a, ull b, ull c) {
    ull d;
    asm("fma.rn.f32x2 %0, %1, %2, %3;" : "=l"(d) : "l"(a), "l"(b), "l"(c));
    return d;
}

// ---------------------------------------------------------------------------
// Scratch (no allocations allowed).
// ---------------------------------------------------------------------------
constexpr size_t N_BUF1 = (size_t)BATCH * 96 * 32 * 32;   // conv1 out
constexpr size_t N_BUF2 = (size_t)BATCH * 96 * 18 * 18;   // pool1 (padded)
constexpr size_t N_BUF3 = (size_t)BATCH * 256 * 16 * 16;  // conv2 out
constexpr size_t N_BUF4 = (size_t)BATCH * 256 * 10 * 10;  // pool2 (padded)
constexpr size_t N_BUF5 = (size_t)BATCH * 384 * 8 * 8;    // conv3 out (unpadded)
constexpr size_t N_BUF6 = (size_t)BATCH * 256 * 6 * 6;    // pcaps out
constexpr size_t N_U    = (size_t)BATCH * 1152 * 8;
constexpr size_t N_BLOG = (size_t)BATCH * 100 * 1152;
constexpr size_t N_C    = (size_t)BATCH * 100 * 1152;
constexpr size_t N_V    = (size_t)BATCH * 100 * 16;
constexpr size_t N_F1   = (size_t)BATCH * 4096;
constexpr size_t N_F2   = (size_t)BATCH * 4096;
constexpr size_t N_XHAT = (size_t)BATCH * 100 * 1152 * 16;

constexpr size_t O_BUF1 = 0;
constexpr size_t O_BUF2 = O_BUF1 + N_BUF1;
constexpr size_t O_BUF3 = O_BUF2 + N_BUF2;
constexpr size_t O_BUF4 = O_BUF3 + N_BUF3;
constexpr size_t O_BUF5 = O_BUF4 + N_BUF4;
constexpr size_t O_BUF6 = O_BUF5 + N_BUF5;
constexpr size_t O_U    = O_BUF6 + N_BUF6;
constexpr size_t O_BLOG = O_U + N_U;
constexpr size_t O_C    = O_BLOG + N_BLOG;
constexpr size_t O_V    = O_C + N_C;
constexpr size_t O_F1   = O_V + N_V;
constexpr size_t O_F2   = O_F1 + N_F1;
constexpr size_t N_TOTAL = O_F2 + N_F2;

__device__ __align__(16) float g_scratch[N_TOTAL];
__device__ __align__(16) __half g_xhat[N_XHAT];

// fp16 weight matrices [K = CIN*9 + 16 bias rows][OC]
constexpr size_t NW2 = (size_t)(96 * 9 + 16) * 256;    // 225280
constexpr size_t NW3 = (size_t)(256 * 9 + 16) * 384;   // 890880
constexpr size_t NWP = (size_t)(384 * 9 + 16) * 256;   // 888832
__device__ __align__(16) __half g_wh[NW2 + NW3 + NWP];

// ---------------------------------------------------------------------------
// Weight prep: fp32 [OC,CIN,3,3] + bias -> fp16 [CIN*9+16, OC].
// k = c*144 + j, j = ic_local*9 + tap (matches P-tile layout); bias row k0 =
// CIN*9 (ones-column trick folds bias into the GEMM).
// ---------------------------------------------------------------------------
__global__ void prep_wconv_kernel(const float* __restrict__ w,
                                  const float* __restrict__ bias,
                                  __half* __restrict__ out, int CIN_, int OC)
{
    int KT = CIN_ * 9 + 16;
    int idx = blockIdx.x * 256 + threadIdx.x;
    if (idx >= KT * OC) return;
    int oc = idx % OC, k = idx / OC;
    float v;
    if (k < CIN_ * 9) {
        int c = k / 144, j = k % 144;
        int ic = c * 16 + j / 9, tap = j % 9;
        v = w[((size_t)oc * CIN_ + ic) * 9 + tap];
    } else {
        int r = k - CIN_ * 9;
        v = (r == 0) ? bias[oc] : 0.f;
    }
    out[(size_t)k * OC + oc] = __float2half(v);
}

// ---------------------------------------------------------------------------
// WMMA fp16 implicit-GEMM 3x3 conv.
//   D[px, oc] = sum_k P[px,k] * W[k,oc],  P = im2col tile (fp16 from fp32 in),
//   bias via ones-column K-chunk; ReLU applied on accumulator fragments.
// Input layout [CIN, HINP, WINP] per image (padded per layer as needed).
// Output [COUTF, HWOUT] per image; col_major fragment store -> channel-major.
// Block 256 threads (8 warps). Grid (pxtiles, ocblocks, BATCH).
// ---------------------------------------------------------------------------
template<int CIN, int HINP, int WINP, int WOUT, int HWOUT, int NPX, int NPXV,
         int COB, int COUTF, int TPW, bool RELU, bool GUARD>
__global__ void convwmma_kernel(const float* __restrict__ in,
                                const __half* __restrict__ wch,
                                float* __restrict__ out)
{
    constexpr int NCT = COB / 16;
    constexpr int NCH = CIN / 16;
    constexpr int PLD = 144;

    extern __shared__ __align__(16) char smem_raw[];
    __half* P  = (__half*)smem_raw;              // NPX x 144
    __half* Ws = P + NPX * PLD;                  // 144 x COB
    float*  Stg = (float*)(Ws + 144 * COB);      // 8 warps x 256 (GUARD only)

    const int tid = threadIdx.x;
    const int wid = tid >> 5;
    const int pxt = blockIdx.x;
    const int oc0 = blockIdx.y * COB;
    const int b   = blockIdx.z;
    const int y0  = pxt * (NPX / WOUT);
    const float* inb = in + (size_t)b * CIN * HINP * WINP;

    wmma::fragment<wmma::accumulator, 16, 16, 16, float> acc[TPW];
    #pragma unroll
    for (int i = 0; i < TPW; i++) wmma::fill_fragment(acc[i], 0.f);

    for (int c = 0; c <= NCH; c++) {
        const bool last = (c == NCH);
        __syncthreads();
        if (!last) {
            const int ic0 = c * 16;
            for (int e = tid; e < NPX * 144; e += 256) {
                int px = e / 144, j = e % 144;
                int icl = j / 9, tap = j % 9;
                int y = y0 + px / WOUT + tap / 3;
                int x = px % WOUT + tap % 3;
                float v = 0.f;
                if (!GUARD || px < NPXV)
                    v = inb[((size_t)(ic0 + icl) * HINP + y) * WINP + x];
                P[px * PLD + j] = __float2half(v);
            }
        } else {
            for (int e = tid; e < NPX * 16; e += 256) {
                int px = e / 16, j = e % 16;
                P[px * PLD + j] = __float2half(j == 0 ? 1.f : 0.f);
            }
        }
        {
            int nrows = last ? 16 : 144;
            int krow0 = c * 144;
            int total8 = nrows * (COB / 8);
            for (int e = tid; e < total8; e += 256) {
                int r = e / (COB / 8), c8 = e % (COB / 8);
                *(uint4*)(Ws + r * COB + c8 * 8) =
                    *(const uint4*)(wch + (size_t)(krow0 + r) * COUTF + oc0 + c8 * 8);
            }
        }
        __syncthreads();
        int nks = last ? 1 : 9;
        for (int s = 0; s < nks; s++) {
            #pragma unroll
            for (int i = 0; i < TPW; i++) {
                int t = wid * TPW + i, rg = t / NCT, ct = t % NCT;
                wmma::fragment<wmma::matrix_a, 16, 16, 16, __half, wmma::row_major> af;
                wmma::fragment<wmma::matrix_b, 16, 16, 16, __half, wmma::row_major> bf;
                wmma::load_matrix_sync(af, P + rg * 16 * PLD + s * 16, PLD);
                wmma::load_matrix_sync(bf, Ws + s * 16 * COB + ct * 16, COB);
                wmma::mma_sync(acc[i], af, bf, acc[i]);
            }
        }
    }

    if (RELU) {
        #pragma unroll
        for (int i = 0; i < TPW; i++)
            for (int e = 0; e < acc[i].num_elements; e++)
                acc[i].x[e] = fmaxf(acc[i].x[e], 0.f);
    }

    if (!GUARD) {
        #pragma unroll
        for (int i = 0; i < TPW; i++) {
            int t = wid * TPW + i, rg = t / NCT, ct = t % NCT;
            float* dst = out + ((size_t)b * COUTF + oc0 + ct * 16) * HWOUT
                         + pxt * NPX + rg * 16;
            wmma::store_matrix_sync(dst, acc[i], HWOUT, wmma::mem_col_major);
        }
    } else {
        float* mystg = Stg + wid * 256;
        #pragma unroll
        for (int i = 0; i < TPW; i++) {
            int t = wid * TPW + i, rg = t / NCT, ct = t % NCT;
            wmma::store_matrix_sync(mystg, acc[i], 16, wmma::mem_col_major);
            __syncwarp();
            int lane = tid & 31;
            for (int e = lane; e < 256; e += 32) {
                int ii = e % 16, j = e / 16;
                int px = rg * 16 + ii;
                if (px < NPXV)
                    out[((size_t)b * COUTF + oc0 + ct * 16 + j) * HWOUT + px] = mystg[e];
            }
            __syncwarp();
        }
    }
}

// ---------------------------------------------------------------------------
// conv1: guarded-load direct fp32 conv (small CIN=3, unchanged from R9).
// ---------------------------------------------------------------------------
template<int CIN, int HIN, int WIN, int COUT, int HOUT, int WOUT, int PAD,
         int ICC, int PPT, int NOCSUB, bool RELU>
__global__ void conv3x3_kernel(const float* __restrict__ in,
                               const float* __restrict__ wt,
                               const float* __restrict__ bias,
                               float* __restrict__ out)
{
    constexpr int NPG = (HOUT * WOUT) / PPT;
    constexpr int NT  = NPG * NOCSUB;
    constexpr int OCB = NOCSUB * 8;
    constexpr int HT  = HIN + 2 * PAD;
    constexpr int WT  = WIN + 2 * PAD;
    constexpr int WTP = WT + 1;

    __shared__ __align__(16) ull in_s2[ICC * HT * WTP];
    __shared__ __align__(16) float w_s[ICC * 9 * OCB];

    const int tid   = threadIdx.x;
    const int ocblk = blockIdx.x;
    const int b     = blockIdx.y;

    const int pg   = tid % NPG;
    const int ocs  = tid / NPG;
    const int row  = pg / (WOUT / PPT);
    const int col0 = (pg % (WOUT / PPT)) * PPT;
    const int oc0  = ocblk * OCB + ocs * 8;

    ull acc2[PPT][4];
    #pragma unroll
    for (int j4 = 0; j4 < 4; j4++) {
        ull bp = pack2(bias[oc0 + 2 * j4], bias[oc0 + 2 * j4 + 1]);
        #pragma unroll
        for (int p = 0; p < PPT; p++) acc2[p][j4] = bp;
    }

    for (int ic0 = 0; ic0 < CIN; ic0 += ICC) {
        __syncthreads();
        for (int idx = tid; idx < ICC * HT * WT; idx += NT) {
            int x  = idx % WT;
            int y  = (idx / WT) % HT;
            int ic = idx / (WT * HT);
            int gy = y - PAD, gx = x - PAD;
            float v = 0.f;
            if (gy >= 0 && gy < HIN && gx >= 0 && gx < WIN)
                v = in[((size_t)(b * CIN + ic0 + ic) * HIN + gy) * WIN + gx];
            in_s2[(ic * HT + y) * WTP + x] = pack2(v, v);
        }
        for (int idx = tid; idx < ICC * 9 * OCB; idx += NT) {
            int oc_l = idx % OCB;
            int tap  = (idx / OCB) % 9;
            int ic   = idx / (OCB * 9);
            w_s[(ic * 9 + tap) * OCB + oc_l] =
                wt[((size_t)(ocblk * OCB + oc_l) * CIN + ic0 + ic) * 9 + tap];
        }
        __syncthreads();

        #pragma unroll
        for (int ic = 0; ic < ICC; ic++) {
            #pragma unroll
            for (int ky = 0; ky < 3; ky++) {
                ull xq[PPT + 2];
                #pragma unroll
                for (int q = 0; q < PPT + 2; q++)
                    xq[q] = in_s2[(ic * HT + row + ky) * WTP + col0 + q];
                #pragma unroll
                for (int kx = 0; kx < 3; kx++) {
                    const ulonglong2* wp = reinterpret_cast<const ulonglong2*>(
                        &w_s[(ic * 9 + ky * 3 + kx) * OCB + ocs * 8]);
                    ulonglong2 wA = wp[0];
                    ulonglong2 wB = wp[1];
                    #pragma unroll
                    for (int p = 0; p < PPT; p++) {
                        ull xv = xq[p + kx];
                        acc2[p][0] = ffma2(xv, wA.x, acc2[p][0]);
                        acc2[p][1] = ffma2(xv, wA.y, acc2[p][1]);
                        acc2[p][2] = ffma2(xv, wB.x, acc2[p][2]);
                        acc2[p][3] = ffma2(xv, wB.y, acc2[p][3]);
                    }
                }
            }
        }
    }

    #pragma unroll
    for (int j4 = 0; j4 < 4; j4++) {
        #pragma unroll
        for (int p = 0; p < PPT; p++) {
            float lo, hi;
            unpack2(acc2[p][j4], lo, hi);
            if (RELU) { lo = fmaxf(lo, 0.f); hi = fmaxf(hi, 0.f); }
            size_t ob = ((size_t)(b * COUT + oc0 + 2 * j4) * HOUT + row) * WOUT + col0 + p;
            out[ob] = lo;
            out[ob + (size_t)HOUT * WOUT] = hi;
        }
    }
}

// ---------------------------------------------------------------------------
// MaxPool 3x3 stride 2 pad 1; optionally writes padded output layout.
// ---------------------------------------------------------------------------
template<int C, int HIN, int OUTPAD>
__global__ void maxpool_kernel(const float* __restrict__ in, float* __restrict__ out)
{
    constexpr int HO = HIN / 2;
    int idx = blockIdx.x * blockDim.x + threadIdx.x;
    if (idx >= BATCH * C * HO * HO) return;
    int ox = idx % HO;
    int oy = (idx / HO) % HO;
    int c  = (idx / (HO * HO)) % C;
    int b  = idx / (HO * HO * C);
    const float* p = in + ((size_t)(b * C + c)) * HIN * HIN;
    float m = -1e30f;
    #pragma unroll
    for (int dy = 0; dy < 3; dy++) {
        int y = 2 * oy - 1 + dy;
        if (y < 0 || y >= HIN) continue;
        #pragma unroll
        for (int dx = 0; dx < 3; dx++) {
            int x = 2 * ox - 1 + dx;
            if (x < 0 || x >= HIN) continue;
            m = fmaxf(m, p[y * HIN + x]);
        }
    }
    if (OUTPAD) {
        constexpr int HOP = HO + 2;
        out[((size_t)(b * C + c) * HOP + oy + 1) * HOP + ox + 1] = m;
    } else {
        out[idx] = m;
    }
}

// ---------------------------------------------------------------------------
// Squash primarycaps: p flat [B,9216] -> u [B,1152,8]
// ---------------------------------------------------------------------------
__global__ void squash_u_kernel(const float* __restrict__ p, float* __restrict__ u)
{
    int cap = blockIdx.x * blockDim.x + threadIdx.x;
    if (cap >= BATCH * 1152) return;
    const float4* s = reinterpret_cast<const float4*>(p + (size_t)cap * 8);
    float4 a = s[0], b4 = s[1];
    float n2 = a.x * a.x + a.y * a.y + a.z * a.z + a.w * a.w +
               b4.x * b4.x + b4.y * b4.y + b4.z * b4.z + b4.w * b4.w;
    float sc = (n2 / (1.f + n2)) * rsqrtf(n2 + 1e-8f);
    float4* o = reinterpret_cast<float4*>(u + (size_t)cap * 8);
    o[0] = make_float4(a.x * sc, a.y * sc, a.z * sc, a.w * sc);
    o[1] = make_float4(b4.x * sc, b4.y * sc, b4.z * sc, b4.w * sc);
}

// ---------------------------------------------------------------------------
// x_hat[b,o,i,d] = sum_e W[o,i,d,e] * u[b,i,e], stored fp16.
// ---------------------------------------------------------------------------
__global__ void xhat16_kernel(const float* __restrict__ Wc,
                              const float* __restrict__ u,
                              __half* __restrict__ xh)
{
    __shared__ float u_s[256];
    const int o  = blockIdx.y;
    const int i0 = blockIdx.x * 32;
    const int tid = threadIdx.x;
    const int il  = tid >> 3;
    const int dp  = tid & 7;

    const float4* wg4 = reinterpret_cast<const float4*>(
        Wc + (((size_t)o * 1152 + i0 + il) * 16 + dp * 2) * 8);
    float4 w0 = wg4[0], w1 = wg4[1], w2 = wg4[2], w3 = wg4[3];
    float wA[8] = {w0.x, w0.y, w0.z, w0.w, w1.x, w1.y, w1.z, w1.w};
    float wB[8] = {w2.x, w2.y, w2.z, w2.w, w3.x, w3.y, w3.z, w3.w};

    for (int b = 0; b < BATCH; b++) {
        __syncthreads();
        u_s[tid] = u[((size_t)b * 1152 + i0) * 8 + tid];
        __syncthreads();
        const float* ur = &u_s[il * 8];
        float a0 = 0.f, a1 = 0.f;
        #pragma unroll
        for (int e = 0; e < 8; e++) {
            a0 = fmaf(wA[e], ur[e], a0);
            a1 = fmaf(wB[e], ur[e], a1);
        }
        *reinterpret_cast<__half2*>(
            xh + (((size_t)b * 100 + o) * 1152 + i0 + il) * 16 + dp * 2) =
            __floats2half2_rn(a0, a1);
    }
}

// ---------------------------------------------------------------------------
// Fused routing iteration (smem-only squash reduction; barriers uniform).
// ---------------------------------------------------------------------------
template<int MODE>
__global__ void route_fused_kernel(const __half* __restrict__ xhat,
                                   const float* __restrict__ c,
                                   float* __restrict__ blog,
                                   float* __restrict__ v)
{
    __shared__ __align__(16) __half xs[1152 * 16];
    __shared__ float cs[1152];
    __shared__ float red[256];
    __shared__ float vs[16];

    const int o = blockIdx.x, b = blockIdx.y, tid = threadIdx.x;
    const size_t base = (size_t)(b * 100 + o);

    const float4* xg = reinterpret_cast<const float4*>(xhat + base * 1152 * 16);
    float4* xs4 = reinterpret_cast<float4*>(xs);
    #pragma unroll
    for (int k = 0; k < 9; k++) xs4[tid + k * 256] = xg[tid + k * 256];

    if (MODE != 0) {
        const float* cg = c + base * 1152;
        for (int i = tid; i < 1152; i += 256) cs[i] = cg[i];
    }
    __syncthreads();

    const int d = tid & 15, ig = tid >> 4;
    float acc = 0.f;
    for (int i = ig; i < 1152; i += 16) {
        float x = __half2float(xs[i * 16 + d]);
        if (MODE == 0) acc += x;
        else           acc = fmaf(cs[i], x, acc);
    }
    red[tid] = acc;
    __syncthreads();
    #pragma unroll
    for (int st = 128; st >= 16; st >>= 1) {
        if (tid < st) red[tid] += red[tid + st];
        __syncthreads();
    }
    if (tid < 16) {
        float s = red[tid];
        if (MODE == 0) s *= 0.01f;
        red[tid] = s;
    }
    __syncthreads();
    if (tid < 16) {
        float n2 = 0.f;
        #pragma unroll
        for (int q = 0; q < 16; q++) n2 += red[q] * red[q];
        float sc = (n2 / (1.f + n2)) * rsqrtf(n2 + 1e-8f);
        float vv = red[tid] * sc;
        vs[tid] = vv;
        if (MODE == 2) v[base * 16 + tid] = vv;
    }
    if (MODE == 2) return;
    __syncthreads();

    float* bl = blog + base * 1152;
    for (int i = tid; i < 1152; i += 256) {
        const float4* xp = reinterpret_cast<const float4*>(xs + i * 16);
        float4 p0 = xp[0], p1 = xp[1];
        const __half2* h0 = reinterpret_cast<const __half2*>(&p0);
        const __half2* h1 = reinterpret_cast<const __half2*>(&p1);
        float dot = 0.f;
        #pragma unroll
        for (int q = 0; q < 4; q++) {
            float2 f = __half22float2(h0[q]);
            dot = fmaf(f.x, vs[q * 2 + 0], dot);
            dot = fmaf(f.y, vs[q * 2 + 1], dot);
        }
        #pragma unroll
        for (int q = 0; q < 4; q++) {
            float2 f = __half22float2(h1[q]);
            dot = fmaf(f.x, vs[8 + q * 2 + 0], dot);
            dot = fmaf(f.y, vs[8 + q * 2 + 1], dot);
        }
        if (MODE == 0) bl[i] = dot;
        else           bl[i] += dot;
    }
}

// ---------------------------------------------------------------------------
// Softmax over o (100 entries) for each (b, i).
// ---------------------------------------------------------------------------
__global__ void softmax_o_kernel(const float* __restrict__ blog, float* __restrict__ c)
{
    __shared__ float t[100][33];
    int i0 = blockIdx.x * 32, b = blockIdx.y, tid = threadIdx.x;
    for (int idx = tid; idx < 100 * 32; idx += 128) {
        int ii = idx % 32, o = idx / 32;
        t[o][ii] = blog[((size_t)(b * 100 + o)) * 1152 + i0 + ii];
    }
    __syncthreads();
    if (tid < 32) {
        float mx = -1e30f;
        for (int o = 0; o < 100; o++) mx = fmaxf(mx, t[o][tid]);
        float sm = 0.f;
        for (int o = 0; o < 100; o++) {
            float e = expf(t[o][tid] - mx);
            t[o][tid] = e;
            sm += e;
        }
        float inv = 1.f / sm;
        for (int o = 0; o < 100; o++) t[o][tid] *= inv;
    }
    __syncthreads();
    for (int idx = tid; idx < 100 * 32; idx += 128) {
        int ii = idx % 32, o = idx / 32;
        c[((size_t)(b * 100 + o)) * 1152 + i0 + ii] = t[o][ii];
    }
}

// ---------------------------------------------------------------------------
// FC with packed f32x2 (unchanged from R9).
// ---------------------------------------------------------------------------
template<bool RELU>
__global__ void fc_kernel(const float* __restrict__ A, const float* __restrict__ Wm,
                          const float* __restrict__ bias, float* __restrict__ C,
                          int K, int N)
{
    __shared__ __align__(16) ull As2[16][66];
    __shared__ __align__(16) float Bs[16][68];
    int tid = threadIdx.x;
    int n0 = blockIdx.x * 64, m0 = blockIdx.y * 64;
    int tx = tid % 16, ty = tid / 16;
    ull acc2[4][2];
    #pragma unroll
    for (int i = 0; i < 4; i++)
        #pragma unroll
        for (int j = 0; j < 2; j++) acc2[i][j] = 0ull;

    for (int k0 = 0; k0 < K; k0 += 16) {
        #pragma unroll
        for (int rep = 0; rep < 4; rep++) {
            int idx = tid + rep * 256;
            int b_l = idx / 16, k_l = idx % 16;
            float a = A[(size_t)(m0 + b_l) * K + k0 + k_l];
            As2[k_l][b_l] = pack2(a, a);
        }
        #pragma unroll
        for (int rep = 0; rep < 4; rep++) {
            int idx = tid + rep * 256;
            int k_l = idx / 64, n_l = idx % 64;
            int n = n0 + n_l;
            Bs[k_l][n_l] = (n < N) ? Wm[(size_t)(k0 + k_l) * N + n] : 0.f;
        }
        __syncthreads();
        #pragma unroll
        for (int k = 0; k < 16; k++) {
            const ulonglong2* bp = reinterpret_cast<const ulonglong2*>(&Bs[k][tx * 4]);
            ulonglong2 bb = bp[0];
            ull a0 = As2[k][ty * 4 + 0];
            ull a1 = As2[k][ty * 4 + 1];
            ull a2 = As2[k][ty * 4 + 2];
            ull a3 = As2[k][ty * 4 + 3];
            acc2[0][0] = ffma2(a0, bb.x, acc2[0][0]);
            acc2[0][1] = ffma2(a0, bb.y, acc2[0][1]);
            acc2[1][0] = ffma2(a1, bb.x, acc2[1][0]);
            acc2[1][1] = ffma2(a1, bb.y, acc2[1][1]);
            acc2[2][0] = ffma2(a2, bb.x, acc2[2][0]);
            acc2[2][1] = ffma2(a2, bb.y, acc2[2][1]);
            acc2[3][0] = ffma2(a3, bb.x, acc2[3][0]);
            acc2[3][1] = ffma2(a3, bb.y, acc2[3][1]);
        }
        __syncthreads();
    }
    #pragma unroll
    for (int i = 0; i < 4; i++) {
        int m = m0 + ty * 4 + i;
        #pragma unroll
        for (int j = 0; j < 2; j++) {
            float lo, hi;
            unpack2(acc2[i][j], lo, hi);
            int n_lo = n0 + tx * 4 + 2 * j;
            int n_hi = n_lo + 1;
            if (n_lo < N) {
                float val = lo + bias[n_lo];
                if (RELU) val = fmaxf(val, 0.f);
                C[(size_t)m * N + n_lo] = val;
            }
            if (n_hi < N) {
                float val = hi + bias[n_hi];
                if (RELU) val = fmaxf(val, 0.f);
                C[(size_t)m * N + n_hi] = val;
            }
        }
    }
}

// ---------------------------------------------------------------------------
// launch
// ---------------------------------------------------------------------------
extern "C" void kernel_launch(void* const* d_in, const int* in_sizes, int n_in,
                              void* d_out, int out_size)
{
    const float* x     = (const float*)d_in[0];
    const float* cw1   = (const float*)d_in[1];
    const float* cb1   = (const float*)d_in[2];
    const float* cw2   = (const float*)d_in[3];
    const float* cb2   = (const float*)d_in[4];
    const float* cw3   = (const float*)d_in[5];
    const float* cb3   = (const float*)d_in[6];
    const float* pw    = (const float*)d_in[7];
    const float* pb    = (const float*)d_in[8];
    const float* Wcaps = (const float*)d_in[9];
    const float* fw1   = (const float*)d_in[10];
    const float* fb1   = (const float*)d_in[11];
    const float* fw2   = (const float*)d_in[12];
    const float* fb2   = (const float*)d_in[13];
    const float* fw3   = (const float*)d_in[14];
    const float* fb3   = (const float*)d_in[15];

    void* sp = nullptr;
    cudaGetSymbolAddress(&sp, g_scratch);
    float* S = (float*)sp;
    void* xp = nullptr;
    cudaGetSymbolAddress(&xp, g_xhat);
    __half* xhat = (__half*)xp;
    void* wp_ = nullptr;
    cudaGetSymbolAddress(&wp_, g_wh);
    __half* w2h = (__half*)wp_;
    __half* w3h = w2h + NW2;
    __half* wph = w3h + NW3;

    float* buf1 = S + O_BUF1;
    float* buf2 = S + O_BUF2;   // padded [96,18,18]
    float* buf3 = S + O_BUF3;
    float* buf4 = S + O_BUF4;   // padded [256,10,10]
    float* buf5 = S + O_BUF5;   // unpadded [384,8,8]
    float* buf6 = S + O_BUF6;
    float* u    = S + O_U;
    float* blog = S + O_BLOG;
    float* cbuf = S + O_C;
    float* v    = S + O_V;
    float* f1   = S + O_F1;
    float* f2   = S + O_F2;
    float* outp = (float*)d_out;

    // zero padded buffers (borders must be 0 every call)
    cudaMemsetAsync(buf2, 0, N_BUF2 * sizeof(float));
    cudaMemsetAsync(buf4, 0, N_BUF4 * sizeof(float));

    // fp16 weight prep
    prep_wconv_kernel<<<(int)((NW2 + 255) / 256), 256>>>(cw2, cb2, w2h, 96, 256);
    prep_wconv_kernel<<<(int)((NW3 + 255) / 256), 256>>>(cw3, cb3, w3h, 256, 384);
    prep_wconv_kernel<<<(int)((NWP + 255) / 256), 256>>>(pw, pb, wph, 384, 256);

    // conv1 fp32
    conv3x3_kernel<3, 32, 32, 96, 32, 32, 1, 3, 4, 1, true>
        <<<dim3(12, BATCH), 256>>>(x, cw1, cb1, buf1);
    maxpool_kernel<96, 32, 1><<<(BATCH * 96 * 16 * 16 + 255) / 256, 256>>>(buf1, buf2);

    // conv2 wmma: in [96,18,18] -> out [256,256]
    {
        constexpr int SM2 = (64 * 144 + 144 * 256) * 2;
        auto kfn = convwmma_kernel<96, 18, 18, 16, 256, 64, 64, 256, 256, 8, true, false>;
        cudaFuncSetAttribute(kfn, cudaFuncAttributeMaxDynamicSharedMemorySize, SM2);
        kfn<<<dim3(4, 1, BATCH), 256, SM2>>>(buf2, w2h, buf3);
    }
    maxpool_kernel<256, 16, 1><<<(BATCH * 256 * 8 * 8 + 255) / 256, 256>>>(buf3, buf4);

    // conv3 wmma: in [256,10,10] -> out [384,64], oc split 2x192
    {
        constexpr int SM3 = (64 * 144 + 144 * 192) * 2;
        auto kfn = convwmma_kernel<256, 10, 10, 8, 64, 64, 64, 192, 384, 6, true, false>;
        cudaFuncSetAttribute(kfn, cudaFuncAttributeMaxDynamicSharedMemorySize, SM3);
        kfn<<<dim3(1, 2, BATCH), 256, SM3>>>(buf4, w3h, buf5);
    }

    // pcaps wmma: in [384,8,8] -> out [256,36], oc split 2x128, px guard 36/48
    {
        constexpr int SMP = (48 * 144 + 144 * 128) * 2 + 8 * 256 * 4;
        auto kfn = convwmma_kernel<384, 8, 8, 6, 36, 48, 36, 128, 256, 3, false, true>;
        cudaFuncSetAttribute(kfn, cudaFuncAttributeMaxDynamicSharedMemorySize, SMP);
        kfn<<<dim3(1, 2, BATCH), 256, SMP>>>(buf5, wph, buf6);
    }

    squash_u_kernel<<<(BATCH * 1152 + 255) / 256, 256>>>(buf6, u);

    // xhat (fp16)
    xhat16_kernel<<<dim3(36, 100), 256>>>(Wcaps, u, xhat);

    // routing: 3 fused iterations, softmax between
    route_fused_kernel<0><<<dim3(100, BATCH), 256>>>(xhat, cbuf, blog, v);
    softmax_o_kernel<<<dim3(36, BATCH), 128>>>(blog, cbuf);
    route_fused_kernel<1><<<dim3(100, BATCH), 256>>>(xhat, cbuf, blog, v);
    softmax_o_kernel<<<dim3(36, BATCH), 128>>>(blog, cbuf);
    route_fused_kernel<2><<<dim3(100, BATCH), 256>>>(xhat, cbuf, blog, v);

    // FC head
    fc_kernel<true><<<dim3(64, 2), 256>>>(v, fw1, fb1, f1, 1600, 4096);
    fc_kernel<true><<<dim3(64, 2), 256>>>(f1, fw2, fb2, f2, 4096, 4096);
    fc_kernel<false><<<dim3(2, 2), 256>>>(f2, fw3, fb3, outp, 4096, 100);

    (void)in_sizes; (void)n_in; (void)out_size;
}

// round 13
// speedup vs baseline: 4.2317x; 1.2629x over previous
#include <cuda_runtime.h>
#include <cuda_fp16.h>
#include <mma.h>
#include <cstddef>
#include <cstdint>
#include <math.h>

using namespace nvcuda;

#define BATCH 128

typedef unsigned long long ull;

// ---------------------------------------------------------------------------
// f32x2 packed helpers.
// ---------------------------------------------------------------------------
__device__ __forceinline__ ull pack2(float lo, float hi) {
    ull r;
    asm("mov.b64 %0, {%1, %2};" : "=l"(r) : "f"(lo), "f"(hi));
    return r;
}
__device__ __forceinline__ void unpack2(ull v, float& lo, float& hi) {
    asm("mov.b64 {%0, %1}, %2;" : "=f"(lo), "=f"(hi) : "l"(v));
}
__device__ __forceinline__ ull ffma2(ull a, ull b, ull c) {
    ull d;
    asm("fma.rn.f32x2 %0, %1, %2, %3;" : "=l"(d) : "l"(a), "l"(b), "l"(c));
    return d;
}

// ---------------------------------------------------------------------------
// Scratch (no allocations allowed).
// ---------------------------------------------------------------------------
constexpr size_t N_BUF1 = (size_t)BATCH * 96 * 32 * 32;   // conv1 out
constexpr size_t N_BUF2 = (size_t)BATCH * 96 * 18 * 18;   // pool1 (padded)
constexpr size_t N_BUF3 = (size_t)BATCH * 256 * 16 * 16;  // conv2 out
constexpr size_t N_BUF4 = (size_t)BATCH * 256 * 10 * 10;  // pool2 (padded)
constexpr size_t N_BUF5 = (size_t)BATCH * 384 * 8 * 8;    // conv3 out (unpadded)
constexpr size_t N_BUF6 = (size_t)BATCH * 256 * 6 * 6;    // pcaps out
constexpr size_t N_U    = (size_t)BATCH * 1152 * 8;
constexpr size_t N_BLOG = (size_t)BATCH * 100 * 1152;
constexpr size_t N_C    = (size_t)BATCH * 100 * 1152;
constexpr size_t N_V    = (size_t)BATCH * 100 * 16;
constexpr size_t N_F1   = (size_t)BATCH * 4096;
constexpr size_t N_F2   = (size_t)BATCH * 4096;
constexpr size_t N_PART = (size_t)8 * 128 * 4096;         // fc split-K partials
constexpr size_t N_XHAT = (size_t)BATCH * 100 * 1152 * 16;

constexpr size_t O_BUF1 = 0;
constexpr size_t O_BUF2 = O_BUF1 + N_BUF1;
constexpr size_t O_BUF3 = O_BUF2 + N_BUF2;
constexpr size_t O_BUF4 = O_BUF3 + N_BUF3;
constexpr size_t O_BUF5 = O_BUF4 + N_BUF4;
constexpr size_t O_BUF6 = O_BUF5 + N_BUF5;
constexpr size_t O_U    = O_BUF6 + N_BUF6;
constexpr size_t O_BLOG = O_U + N_U;
constexpr size_t O_C    = O_BLOG + N_BLOG;
constexpr size_t O_V    = O_C + N_C;
constexpr size_t O_F1   = O_V + N_V;
constexpr size_t O_F2   = O_F1 + N_F1;
constexpr size_t O_PART = O_F2 + N_F2;
constexpr size_t N_TOTAL = O_PART + N_PART;

__device__ __align__(16) float g_scratch[N_TOTAL];
__device__ __align__(16) __half g_xhat[N_XHAT];

// fp16 weight matrices [K = CIN*9 + 16 bias rows][OC]
constexpr size_t NW2 = (size_t)(96 * 9 + 16) * 256;
constexpr size_t NW3 = (size_t)(256 * 9 + 16) * 384;
constexpr size_t NWP = (size_t)(384 * 9 + 16) * 256;
__device__ __align__(16) __half g_wh[NW2 + NW3 + NWP];

// ---------------------------------------------------------------------------
// Weight prep: fp32 [OC,CIN,3,3] + bias -> fp16 [CIN*9+16, OC].
// ---------------------------------------------------------------------------
__global__ void prep_wconv_kernel(const float* __restrict__ w,
                                  const float* __restrict__ bias,
                                  __half* __restrict__ out, int CIN_, int OC)
{
    int KT = CIN_ * 9 + 16;
    int idx = blockIdx.x * 256 + threadIdx.x;
    if (idx >= KT * OC) return;
    int oc = idx % OC, k = idx / OC;
    float v;
    if (k < CIN_ * 9) {
        int c = k / 144, j = k % 144;
        int ic = c * 16 + j / 9, tap = j % 9;
        v = w[((size_t)oc * CIN_ + ic) * 9 + tap];
    } else {
        int r = k - CIN_ * 9;
        v = (r == 0) ? bias[oc] : 0.f;
    }
    out[(size_t)k * OC + oc] = __float2half(v);
}

// ---------------------------------------------------------------------------
// WMMA fp16 implicit-GEMM 3x3 conv (vectorized 9-tap im2col P-build).
// ---------------------------------------------------------------------------
template<int CIN, int HINP, int WINP, int WOUT, int HWOUT, int NPX, int NPXV,
         int COB, int COUTF, int TPW, bool RELU, bool GUARD>
__global__ void convwmma_kernel(const float* __restrict__ in,
                                const __half* __restrict__ wch,
                                float* __restrict__ out)
{
    constexpr int NCT = COB / 16;
    constexpr int NCH = CIN / 16;
    constexpr int PLD = 144;

    extern __shared__ __align__(16) char smem_raw[];
    __half* P  = (__half*)smem_raw;              // NPX x 144
    __half* Ws = P + NPX * PLD;                  // 144 x COB
    float*  Stg = (float*)(Ws + 144 * COB);      // 8 warps x 256 (GUARD only)

    const int tid = threadIdx.x;
    const int wid = tid >> 5;
    const int pxt = blockIdx.x;
    const int oc0 = blockIdx.y * COB;
    const int b   = blockIdx.z;
    const int y0  = pxt * (NPX / WOUT);
    const float* inb = in + (size_t)b * CIN * HINP * WINP;

    wmma::fragment<wmma::accumulator, 16, 16, 16, float> acc[TPW];
    #pragma unroll
    for (int i = 0; i < TPW; i++) wmma::fill_fragment(acc[i], 0.f);

    for (int c = 0; c <= NCH; c++) {
        const bool last = (c == NCH);
        __syncthreads();
        if (!last) {
            const int ic0 = c * 16;
            for (int e = tid; e < NPX * 16; e += 256) {
                int px  = e >> 4;
                int icl = e & 15;
                int y = y0 + px / WOUT;
                int x = px % WOUT;
                __half* dst = P + px * PLD + icl * 9;
                if (!GUARD || px < NPXV) {
                    const float* src =
                        inb + ((size_t)(ic0 + icl) * HINP + y) * WINP + x;
                    #pragma unroll
                    for (int r = 0; r < 3; r++) {
                        float a0 = src[r * WINP + 0];
                        float a1 = src[r * WINP + 1];
                        float a2 = src[r * WINP + 2];
                        dst[r * 3 + 0] = __float2half(a0);
                        dst[r * 3 + 1] = __float2half(a1);
                        dst[r * 3 + 2] = __float2half(a2);
                    }
                } else {
                    #pragma unroll
                    for (int t = 0; t < 9; t++) dst[t] = __float2half(0.f);
                }
            }
        } else {
            for (int e = tid; e < NPX * 16; e += 256) {
                int px = e / 16, j = e % 16;
                P[px * PLD + j] = __float2half(j == 0 ? 1.f : 0.f);
            }
        }
        {
            int nrows = last ? 16 : 144;
            int krow0 = c * 144;
            int total8 = nrows * (COB / 8);
            for (int e = tid; e < total8; e += 256) {
                int r = e / (COB / 8), c8 = e % (COB / 8);
                *(uint4*)(Ws + r * COB + c8 * 8) =
                    *(const uint4*)(wch + (size_t)(krow0 + r) * COUTF + oc0 + c8 * 8);
            }
        }
        __syncthreads();
        int nks = last ? 1 : 9;
        for (int s = 0; s < nks; s++) {
            #pragma unroll
            for (int i = 0; i < TPW; i++) {
                int t = wid * TPW + i, rg = t / NCT, ct = t % NCT;
                wmma::fragment<wmma::matrix_a, 16, 16, 16, __half, wmma::row_major> af;
                wmma::fragment<wmma::matrix_b, 16, 16, 16, __half, wmma::row_major> bf;
                wmma::load_matrix_sync(af, P + rg * 16 * PLD + s * 16, PLD);
                wmma::load_matrix_sync(bf, Ws + s * 16 * COB + ct * 16, COB);
                wmma::mma_sync(acc[i], af, bf, acc[i]);
            }
        }
    }

    if (RELU) {
        #pragma unroll
        for (int i = 0; i < TPW; i++)
            for (int e = 0; e < acc[i].num_elements; e++)
                acc[i].x[e] = fmaxf(acc[i].x[e], 0.f);
    }

    if (!GUARD) {
        #pragma unroll
        for (int i = 0; i < TPW; i++) {
            int t = wid * TPW + i, rg = t / NCT, ct = t % NCT;
            float* dst = out + ((size_t)b * COUTF + oc0 + ct * 16) * HWOUT
                         + pxt * NPX + rg * 16;
            wmma::store_matrix_sync(dst, acc[i], HWOUT, wmma::mem_col_major);
        }
    } else {
        float* mystg = Stg + wid * 256;
        #pragma unroll
        for (int i = 0; i < TPW; i++) {
            int t = wid * TPW + i, rg = t / NCT, ct = t % NCT;
            wmma::store_matrix_sync(mystg, acc[i], 16, wmma::mem_col_major);
            __syncwarp();
            int lane = tid & 31;
            for (int e = lane; e < 256; e += 32) {
                int ii = e % 16, j = e / 16;
                int px = rg * 16 + ii;
                if (px < NPXV)
                    out[((size_t)b * COUTF + oc0 + ct * 16 + j) * HWOUT + px] = mystg[e];
            }
            __syncwarp();
        }
    }
}

// ---------------------------------------------------------------------------
// conv1: guarded-load direct fp32 conv (small CIN=3).
// ---------------------------------------------------------------------------
template<int CIN, int HIN, int WIN, int COUT, int HOUT, int WOUT, int PAD,
         int ICC, int PPT, int NOCSUB, bool RELU>
__global__ void conv3x3_kernel(const float* __restrict__ in,
                               const float* __restrict__ wt,
                               const float* __restrict__ bias,
                               float* __restrict__ out)
{
    constexpr int NPG = (HOUT * WOUT) / PPT;
    constexpr int NT  = NPG * NOCSUB;
    constexpr int OCB = NOCSUB * 8;
    constexpr int HT  = HIN + 2 * PAD;
    constexpr int WT  = WIN + 2 * PAD;
    constexpr int WTP = WT + 1;

    __shared__ __align__(16) ull in_s2[ICC * HT * WTP];
    __shared__ __align__(16) float w_s[ICC * 9 * OCB];

    const int tid   = threadIdx.x;
    const int ocblk = blockIdx.x;
    const int b     = blockIdx.y;

    const int pg   = tid % NPG;
    const int ocs  = tid / NPG;
    const int row  = pg / (WOUT / PPT);
    const int col0 = (pg % (WOUT / PPT)) * PPT;
    const int oc0  = ocblk * OCB + ocs * 8;

    ull acc2[PPT][4];
    #pragma unroll
    for (int j4 = 0; j4 < 4; j4++) {
        ull bp = pack2(bias[oc0 + 2 * j4], bias[oc0 + 2 * j4 + 1]);
        #pragma unroll
        for (int p = 0; p < PPT; p++) acc2[p][j4] = bp;
    }

    for (int ic0 = 0; ic0 < CIN; ic0 += ICC) {
        __syncthreads();
        for (int idx = tid; idx < ICC * HT * WT; idx += NT) {
            int x  = idx % WT;
            int y  = (idx / WT) % HT;
            int ic = idx / (WT * HT);
            int gy = y - PAD, gx = x - PAD;
            float v = 0.f;
            if (gy >= 0 && gy < HIN && gx >= 0 && gx < WIN)
                v = in[((size_t)(b * CIN + ic0 + ic) * HIN + gy) * WIN + gx];
            in_s2[(ic * HT + y) * WTP + x] = pack2(v, v);
        }
        for (int idx = tid; idx < ICC * 9 * OCB; idx += NT) {
            int oc_l = idx % OCB;
            int tap  = (idx / OCB) % 9;
            int ic   = idx / (OCB * 9);
            w_s[(ic * 9 + tap) * OCB + oc_l] =
                wt[((size_t)(ocblk * OCB + oc_l) * CIN + ic0 + ic) * 9 + tap];
        }
        __syncthreads();

        #pragma unroll
        for (int ic = 0; ic < ICC; ic++) {
            #pragma unroll
            for (int ky = 0; ky < 3; ky++) {
                ull xq[PPT + 2];
                #pragma unroll
                for (int q = 0; q < PPT + 2; q++)
                    xq[q] = in_s2[(ic * HT + row + ky) * WTP + col0 + q];
                #pragma unroll
                for (int kx = 0; kx < 3; kx++) {
                    const ulonglong2* wp = reinterpret_cast<const ulonglong2*>(
                        &w_s[(ic * 9 + ky * 3 + kx) * OCB + ocs * 8]);
                    ulonglong2 wA = wp[0];
                    ulonglong2 wB = wp[1];
                    #pragma unroll
                    for (int p = 0; p < PPT; p++) {
                        ull xv = xq[p + kx];
                        acc2[p][0] = ffma2(xv, wA.x, acc2[p][0]);
                        acc2[p][1] = ffma2(xv, wA.y, acc2[p][1]);
                        acc2[p][2] = ffma2(xv, wB.x, acc2[p][2]);
                        acc2[p][3] = ffma2(xv, wB.y, acc2[p][3]);
                    }
                }
            }
        }
    }

    #pragma unroll
    for (int j4 = 0; j4 < 4; j4++) {
        #pragma unroll
        for (int p = 0; p < PPT; p++) {
            float lo, hi;
            unpack2(acc2[p][j4], lo, hi);
            if (RELU) { lo = fmaxf(lo, 0.f); hi = fmaxf(hi, 0.f); }
            size_t ob = ((size_t)(b * COUT + oc0 + 2 * j4) * HOUT + row) * WOUT + col0 + p;
            out[ob] = lo;
            out[ob + (size_t)HOUT * WOUT] = hi;
        }
    }
}

// ---------------------------------------------------------------------------
// MaxPool 3x3 stride 2 pad 1; optionally writes padded output layout.
// ---------------------------------------------------------------------------
template<int C, int HIN, int OUTPAD>
__global__ void maxpool_kernel(const float* __restrict__ in, float* __restrict__ out)
{
    constexpr int HO = HIN / 2;
    int idx = blockIdx.x * blockDim.x + threadIdx.x;
    if (idx >= BATCH * C * HO * HO) return;
    int ox = idx % HO;
    int oy = (idx / HO) % HO;
    int c  = (idx / (HO * HO)) % C;
    int b  = idx / (HO * HO * C);
    const float* p = in + ((size_t)(b * C + c)) * HIN * HIN;
    float m = -1e30f;
    #pragma unroll
    for (int dy = 0; dy < 3; dy++) {
        int y = 2 * oy - 1 + dy;
        if (y < 0 || y >= HIN) continue;
        #pragma unroll
        for (int dx = 0; dx < 3; dx++) {
            int x = 2 * ox - 1 + dx;
            if (x < 0 || x >= HIN) continue;
            m = fmaxf(m, p[y * HIN + x]);
        }
    }
    if (OUTPAD) {
        constexpr int HOP = HO + 2;
        out[((size_t)(b * C + c) * HOP + oy + 1) * HOP + ox + 1] = m;
    } else {
        out[idx] = m;
    }
}

// ---------------------------------------------------------------------------
// Squash primarycaps: p flat [B,9216] -> u [B,1152,8]
// ---------------------------------------------------------------------------
__global__ void squash_u_kernel(const float* __restrict__ p, float* __restrict__ u)
{
    int cap = blockIdx.x * blockDim.x + threadIdx.x;
    if (cap >= BATCH * 1152) return;
    const float4* s = reinterpret_cast<const float4*>(p + (size_t)cap * 8);
    float4 a = s[0], b4 = s[1];
    float n2 = a.x * a.x + a.y * a.y + a.z * a.z + a.w * a.w +
               b4.x * b4.x + b4.y * b4.y + b4.z * b4.z + b4.w * b4.w;
    float sc = (n2 / (1.f + n2)) * rsqrtf(n2 + 1e-8f);
    float4* o = reinterpret_cast<float4*>(u + (size_t)cap * 8);
    o[0] = make_float4(a.x * sc, a.y * sc, a.z * sc, a.w * sc);
    o[1] = make_float4(b4.x * sc, b4.y * sc, b4.z * sc, b4.w * sc);
}

// ---------------------------------------------------------------------------
// x_hat[b,o,i,d] = sum_e W[o,i,d,e] * u[b,i,e], stored fp16.
// ---------------------------------------------------------------------------
__global__ void xhat16_kernel(const float* __restrict__ Wc,
                              const float* __restrict__ u,
                              __half* __restrict__ xh)
{
    __shared__ float u_s[256];
    const int o  = blockIdx.y;
    const int i0 = blockIdx.x * 32;
    const int tid = threadIdx.x;
    const int il  = tid >> 3;
    const int dp  = tid & 7;

    const float4* wg4 = reinterpret_cast<const float4*>(
        Wc + (((size_t)o * 1152 + i0 + il) * 16 + dp * 2) * 8);
    float4 w0 = wg4[0], w1 = wg4[1], w2 = wg4[2], w3 = wg4[3];
    float wA[8] = {w0.x, w0.y, w0.z, w0.w, w1.x, w1.y, w1.z, w1.w};
    float wB[8] = {w2.x, w2.y, w2.z, w2.w, w3.x, w3.y, w3.z, w3.w};

    for (int b = 0; b < BATCH; b++) {
        __syncthreads();
        u_s[tid] = u[((size_t)b * 1152 + i0) * 8 + tid];
        __syncthreads();
        const float* ur = &u_s[il * 8];
        float a0 = 0.f, a1 = 0.f;
        #pragma unroll
        for (int e = 0; e < 8; e++) {
            a0 = fmaf(wA[e], ur[e], a0);
            a1 = fmaf(wB[e], ur[e], a1);
        }
        *reinterpret_cast<__half2*>(
            xh + (((size_t)b * 100 + o) * 1152 + i0 + il) * 16 + dp * 2) =
            __floats2half2_rn(a0, a1);
    }
}

// ---------------------------------------------------------------------------
// Fused routing iteration (smem-only squash reduction; barriers uniform).
// ---------------------------------------------------------------------------
template<int MODE>
__global__ void route_fused_kernel(const __half* __restrict__ xhat,
                                   const float* __restrict__ c,
                                   float* __restrict__ blog,
                                   float* __restrict__ v)
{
    __shared__ __align__(16) __half xs[1152 * 16];
    __shared__ float cs[1152];
    __shared__ float red[256];
    __shared__ float vs[16];

    const int o = blockIdx.x, b = blockIdx.y, tid = threadIdx.x;
    const size_t base = (size_t)(b * 100 + o);

    const float4* xg = reinterpret_cast<const float4*>(xhat + base * 1152 * 16);
    float4* xs4 = reinterpret_cast<float4*>(xs);
    #pragma unroll
    for (int k = 0; k < 9; k++) xs4[tid + k * 256] = xg[tid + k * 256];

    if (MODE != 0) {
        const float* cg = c + base * 1152;
        for (int i = tid; i < 1152; i += 256) cs[i] = cg[i];
    }
    __syncthreads();

    const int d = tid & 15, ig = tid >> 4;
    float acc = 0.f;
    for (int i = ig; i < 1152; i += 16) {
        float x = __half2float(xs[i * 16 + d]);
        if (MODE == 0) acc += x;
        else           acc = fmaf(cs[i], x, acc);
    }
    red[tid] = acc;
    __syncthreads();
    #pragma unroll
    for (int st = 128; st >= 16; st >>= 1) {
        if (tid < st) red[tid] += red[tid + st];
        __syncthreads();
    }
    if (tid < 16) {
        float s = red[tid];
        if (MODE == 0) s *= 0.01f;
        red[tid] = s;
    }
    __syncthreads();
    if (tid < 16) {
        float n2 = 0.f;
        #pragma unroll
        for (int q = 0; q < 16; q++) n2 += red[q] * red[q];
        float sc = (n2 / (1.f + n2)) * rsqrtf(n2 + 1e-8f);
        float vv = red[tid] * sc;
        vs[tid] = vv;
        if (MODE == 2) v[base * 16 + tid] = vv;
    }
    if (MODE == 2) return;
    __syncthreads();

    float* bl = blog + base * 1152;
    for (int i = tid; i < 1152; i += 256) {
        const float4* xp = reinterpret_cast<const float4*>(xs + i * 16);
        float4 p0 = xp[0], p1 = xp[1];
        const __half2* h0 = reinterpret_cast<const __half2*>(&p0);
        const __half2* h1 = reinterpret_cast<const __half2*>(&p1);
        float dot = 0.f;
        #pragma unroll
        for (int q = 0; q < 4; q++) {
            float2 f = __half22float2(h0[q]);
            dot = fmaf(f.x, vs[q * 2 + 0], dot);
            dot = fmaf(f.y, vs[q * 2 + 1], dot);
        }
        #pragma unroll
        for (int q = 0; q < 4; q++) {
            float2 f = __half22float2(h1[q]);
            dot = fmaf(f.x, vs[8 + q * 2 + 0], dot);
            dot = fmaf(f.y, vs[8 + q * 2 + 1], dot);
        }
        if (MODE == 0) bl[i] = dot;
        else           bl[i] += dot;
    }
}

// ---------------------------------------------------------------------------
// Softmax over o (100 entries) per (b,i): 4-way segmented reduction.
// ---------------------------------------------------------------------------
__global__ void softmax_o_kernel(const float* __restrict__ blog, float* __restrict__ c)
{
    __shared__ float t[100][33];
    __shared__ float red4[4][33];
    __shared__ float sum4[4][33];
    int i0 = blockIdx.x * 32, b = blockIdx.y, tid = threadIdx.x;
    for (int idx = tid; idx < 100 * 32; idx += 128) {
        int ii = idx % 32, o = idx / 32;
        t[o][ii] = blog[((size_t)(b * 100 + o)) * 1152 + i0 + ii];
    }
    __syncthreads();
    int ii = tid & 31, seg = tid >> 5;
    int o0 = seg * 25, o1 = o0 + 25;
    float mx = -1e30f;
    for (int o = o0; o < o1; o++) mx = fmaxf(mx, t[o][ii]);
    red4[seg][ii] = mx;
    __syncthreads();
    float m4 = fmaxf(fmaxf(red4[0][ii], red4[1][ii]),
                     fmaxf(red4[2][ii], red4[3][ii]));
    float sm = 0.f;
    for (int o = o0; o < o1; o++) {
        float e = expf(t[o][ii] - m4);
        t[o][ii] = e;
        sm += e;
    }
    sum4[seg][ii] = sm;
    __syncthreads();
    float inv = 1.f / (sum4[0][ii] + sum4[1][ii] + sum4[2][ii] + sum4[3][ii]);
    for (int o = o0; o < o1; o++) t[o][ii] *= inv;
    __syncthreads();
    for (int idx = tid; idx < 100 * 32; idx += 128) {
        int i2 = idx % 32, o = idx / 32;
        c[((size_t)(b * 100 + o)) * 1152 + i0 + i2] = t[o][i2];
    }
}

// ---------------------------------------------------------------------------
// FC split-K partial GEMM: part[z][m][n] = A[m, z*kch : (z+1)*kch] @ W-chunk.
// 64x64 tile, packed f32x2, no bias/act. M fixed = 128.
// ---------------------------------------------------------------------------
__global__ void fc_part_kernel(const float* __restrict__ A,
                               const float* __restrict__ Wm,
                               float* __restrict__ part,
                               int K_, int N, int kch)
{
    __shared__ __align__(16) ull As2[16][66];
    __shared__ __align__(16) float Bs[16][68];
    int tid = threadIdx.x;
    int n0 = blockIdx.x * 64, m0 = blockIdx.y * 64;
    int kbase = blockIdx.z * kch;
    int tx = tid % 16, ty = tid / 16;
    ull acc2[4][2];
    #pragma unroll
    for (int i = 0; i < 4; i++)
        #pragma unroll
        for (int j = 0; j < 2; j++) acc2[i][j] = 0ull;

    for (int k0 = kbase; k0 < kbase + kch; k0 += 16) {
        #pragma unroll
        for (int rep = 0; rep < 4; rep++) {
            int idx = tid + rep * 256;
            int b_l = idx / 16, k_l = idx % 16;
            float a = A[(size_t)(m0 + b_l) * K_ + k0 + k_l];
            As2[k_l][b_l] = pack2(a, a);
        }
        #pragma unroll
        for (int rep = 0; rep < 4; rep++) {
            int idx = tid + rep * 256;
            int k_l = idx / 64, n_l = idx % 64;
            int n = n0 + n_l;
            Bs[k_l][n_l] = (n < N) ? Wm[(size_t)(k0 + k_l) * N + n] : 0.f;
        }
        __syncthreads();
        #pragma unroll
        for (int k = 0; k < 16; k++) {
            const ulonglong2* bp = reinterpret_cast<const ulonglong2*>(&Bs[k][tx * 4]);
            ulonglong2 bb = bp[0];
            ull a0 = As2[k][ty * 4 + 0];
            ull a1 = As2[k][ty * 4 + 1];
            ull a2 = As2[k][ty * 4 + 2];
            ull a3 = As2[k][ty * 4 + 3];
            acc2[0][0] = ffma2(a0, bb.x, acc2[0][0]);
            acc2[0][1] = ffma2(a0, bb.y, acc2[0][1]);
            acc2[1][0] = ffma2(a1, bb.x, acc2[1][0]);
            acc2[1][1] = ffma2(a1, bb.y, acc2[1][1]);
            acc2[2][0] = ffma2(a2, bb.x, acc2[2][0]);
            acc2[2][1] = ffma2(a2, bb.y, acc2[2][1]);
            acc2[3][0] = ffma2(a3, bb.x, acc2[3][0]);
            acc2[3][1] = ffma2(a3, bb.y, acc2[3][1]);
        }
        __syncthreads();
    }
    float* pz = part + (size_t)blockIdx.z * 128 * N;
    #pragma unroll
    for (int i = 0; i < 4; i++) {
        int m = m0 + ty * 4 + i;
        #pragma unroll
        for (int j = 0; j < 2; j++) {
            float lo, hi;
            unpack2(acc2[i][j], lo, hi);
            int n_lo = n0 + tx * 4 + 2 * j;
            int n_hi = n_lo + 1;
            if (n_lo < N) pz[(size_t)m * N + n_lo] = lo;
            if (n_hi < N) pz[(size_t)m * N + n_hi] = hi;
        }
    }
}

template<bool RELU>
__global__ void fc_reduce_kernel(const float* __restrict__ part,
                                 const float* __restrict__ bias,
                                 float* __restrict__ C, int N, int ksplit)
{
    int idx = blockIdx.x * 256 + threadIdx.x;
    if (idx >= 128 * N) return;
    int n = idx % N, m = idx / N;
    float s = bias[n];
    for (int q = 0; q < ksplit; q++)
        s += part[((size_t)q * 128 + m) * N + n];
    if (RELU) s = fmaxf(s, 0.f);
    C[idx] = s;
}

// ---------------------------------------------------------------------------
// launch
// ---------------------------------------------------------------------------
extern "C" void kernel_launch(void* const* d_in, const int* in_sizes, int n_in,
                              void* d_out, int out_size)
{
    const float* x     = (const float*)d_in[0];
    const float* cw1   = (const float*)d_in[1];
    const float* cb1   = (const float*)d_in[2];
    const float* cw2   = (const float*)d_in[3];
    const float* cb2   = (const float*)d_in[4];
    const float* cw3   = (const float*)d_in[5];
    const float* cb3   = (const float*)d_in[6];
    const float* pw    = (const float*)d_in[7];
    const float* pb    = (const float*)d_in[8];
    const float* Wcaps = (const float*)d_in[9];
    const float* fw1   = (const float*)d_in[10];
    const float* fb1   = (const float*)d_in[11];
    const float* fw2   = (const float*)d_in[12];
    const float* fb2   = (const float*)d_in[13];
    const float* fw3   = (const float*)d_in[14];
    const float* fb3   = (const float*)d_in[15];

    void* sp = nullptr;
    cudaGetSymbolAddress(&sp, g_scratch);
    float* S = (float*)sp;
    void* xp = nullptr;
    cudaGetSymbolAddress(&xp, g_xhat);
    __half* xhat = (__half*)xp;
    void* wp_ = nullptr;
    cudaGetSymbolAddress(&wp_, g_wh);
    __half* w2h = (__half*)wp_;
    __half* w3h = w2h + NW2;
    __half* wph = w3h + NW3;

    float* buf1 = S + O_BUF1;
    float* buf2 = S + O_BUF2;   // padded [96,18,18]
    float* buf3 = S + O_BUF3;
    float* buf4 = S + O_BUF4;   // padded [256,10,10]
    float* buf5 = S + O_BUF5;   // unpadded [384,8,8]
    float* buf6 = S + O_BUF6;
    float* u    = S + O_U;
    float* blog = S + O_BLOG;
    float* cbuf = S + O_C;
    float* v    = S + O_V;
    float* f1   = S + O_F1;
    float* f2   = S + O_F2;
    float* partb = S + O_PART;
    float* outp = (float*)d_out;

    cudaMemsetAsync(buf2, 0, N_BUF2 * sizeof(float));
    cudaMemsetAsync(buf4, 0, N_BUF4 * sizeof(float));

    prep_wconv_kernel<<<(int)((NW2 + 255) / 256), 256>>>(cw2, cb2, w2h, 96, 256);
    prep_wconv_kernel<<<(int)((NW3 + 255) / 256), 256>>>(cw3, cb3, w3h, 256, 384);
    prep_wconv_kernel<<<(int)((NWP + 255) / 256), 256>>>(pw, pb, wph, 384, 256);

    // conv1 fp32
    conv3x3_kernel<3, 32, 32, 96, 32, 32, 1, 3, 4, 1, true>
        <<<dim3(12, BATCH), 256>>>(x, cw1, cb1, buf1);
    maxpool_kernel<96, 32, 1><<<(BATCH * 96 * 16 * 16 + 255) / 256, 256>>>(buf1, buf2);

    // conv2 wmma: in [96,18,18] -> out [256,256]
    {
        constexpr int SM2 = (64 * 144 + 144 * 256) * 2;
        auto kfn = convwmma_kernel<96, 18, 18, 16, 256, 64, 64, 256, 256, 8, true, false>;
        cudaFuncSetAttribute(kfn, cudaFuncAttributeMaxDynamicSharedMemorySize, SM2);
        kfn<<<dim3(4, 1, BATCH), 256, SM2>>>(buf2, w2h, buf3);
    }
    maxpool_kernel<256, 16, 1><<<(BATCH * 256 * 8 * 8 + 255) / 256, 256>>>(buf3, buf4);

    // conv3 wmma: in [256,10,10] -> out [384,64], oc split 2x192
    {
        constexpr int SM3 = (64 * 144 + 144 * 192) * 2;
        auto kfn = convwmma_kernel<256, 10, 10, 8, 64, 64, 64, 192, 384, 6, true, false>;
        cudaFuncSetAttribute(kfn, cudaFuncAttributeMaxDynamicSharedMemorySize, SM3);
        kfn<<<dim3(1, 2, BATCH), 256, SM3>>>(buf4, w3h, buf5);
    }

    // pcaps wmma: in [384,8,8] -> out [256,36], oc split 2x128, px guard 36/48
    {
        constexpr int SMP = (48 * 144 + 144 * 128) * 2 + 8 * 256 * 4;
        auto kfn = convwmma_kernel<384, 8, 8, 6, 36, 48, 36, 128, 256, 3, false, true>;
        cudaFuncSetAttribute(kfn, cudaFuncAttributeMaxDynamicSharedMemorySize, SMP);
        kfn<<<dim3(1, 2, BATCH), 256, SMP>>>(buf5, wph, buf6);
    }

    squash_u_kernel<<<(BATCH * 1152 + 255) / 256, 256>>>(buf6, u);

    // xhat (fp16)
    xhat16_kernel<<<dim3(36, 100), 256>>>(Wcaps, u, xhat);

    // routing: 3 fused iterations, softmax between
    route_fused_kernel<0><<<dim3(100, BATCH), 256>>>(xhat, cbuf, blog, v);
    softmax_o_kernel<<<dim3(36, BATCH), 128>>>(blog, cbuf);
    route_fused_kernel<1><<<dim3(100, BATCH), 256>>>(xhat, cbuf, blog, v);
    softmax_o_kernel<<<dim3(36, BATCH), 128>>>(blog, cbuf);
    route_fused_kernel<2><<<dim3(100, BATCH), 256>>>(xhat, cbuf, blog, v);

    // FC head (split-K + reduce)
    fc_part_kernel<<<dim3(64, 2, 4), 256>>>(v, fw1, partb, 1600, 4096, 400);
    fc_reduce_kernel<true><<<(128 * 4096 + 255) / 256, 256>>>(partb, fb1, f1, 4096, 4);
    fc_part_kernel<<<dim3(64, 2, 8), 256>>>(f1, fw2, partb, 4096, 4096, 512);
    fc_reduce_kernel<true><<<(128 * 4096 + 255) / 256, 256>>>(partb, fb2, f2, 4096, 8);
    fc_part_kernel<<<dim3(2, 2, 32), 256>>>(f2, fw3, partb, 4096, 100, 128);
    fc_reduce_kernel<false><<<(128 * 100 + 255) / 256, 256>>>(partb, fb3, outp, 100, 32);

    (void)in_sizes; (void)n_in; (void)out_size;
}